// round 14
// baseline (speedup 1.0000x reference)
#include <cuda_runtime.h>
#include <cuda_bf16.h>
#include <stdint.h>

// ---------------------------------------------------------------------------
// EGNN / SpatialNCA step.  N=50000 nodes, D=64, E=800000 edges, P=2.
//
// R14 = R13 + occupancy push: TILE_E=288, 576 threads (18 warps, 219KB smem,
// 1 CTA/SM). Gather unroll limited to contain register pressure (112 cap).
// ---------------------------------------------------------------------------

typedef unsigned long long ull;

#define MAXN 50000
#define MAXD 64
#define MAXE 800000

// scratch (device globals: allocation-free rule)
__device__ __align__(16) float d_hsum[MAXN * MAXD];
__device__ __align__(16) __nv_bfloat16 d_hsum_hi[MAXN * MAXD];
__device__ __align__(16) __nv_bfloat16 d_hsum_lo[MAXN * MAXD];
__device__ __align__(16) float d_agg[MAXN * MAXD];
__device__ __align__(16) float d_posacc[MAXN * 2];
__device__ float d_deg[MAXN];
__device__ int   d_src[MAXE];
__device__ int   d_dst[MAXE];
__device__ int   d_e32flag;   // 1 if edge_index buffer is int32, 0 if int64

// ---- small helpers ----------------------------------------------------------
__device__ __forceinline__ uint32_t smem_to_u32(const void* p) {
    uint32_t a;
    asm("{ .reg .u64 t; cvta.to.shared.u64 t, %1; cvt.u32.u64 %0, t; }"
        : "=r"(a) : "l"(p));
    return a;
}
__device__ __forceinline__ float silu_f(float x) {
    return x / (1.0f + __expf(-x));
}
__device__ __forceinline__ void red_add_v2(float* p, float x, float y) {
    asm volatile("red.global.add.v2.f32 [%0], {%1, %2};"
                 :: "l"(p), "f"(x), "f"(y) : "memory");
}
__device__ __forceinline__ ull pk2(float lo, float hi) {
    ull r; asm("mov.b64 %0, {%1,%2};" : "=l"(r) : "f"(lo), "f"(hi)); return r;
}
__device__ __forceinline__ void upk2(ull v, float& lo, float& hi) {
    asm("mov.b64 {%0,%1}, %2;" : "=f"(lo), "=f"(hi) : "l"(v));
}
__device__ __forceinline__ ull fma2(ull a, ull b, ull c) {
    ull d; asm("fma.rn.f32x2 %0, %1, %2, %3;" : "=l"(d) : "l"(a), "l"(b), "l"(c));
    return d;
}

// ---- mma / ldmatrix primitives (sm_80-compatible, run on sm_100 HMMA) -------
__device__ __forceinline__ void ldsm_x4(uint32_t& r0, uint32_t& r1,
                                        uint32_t& r2, uint32_t& r3, uint32_t addr) {
    asm volatile("ldmatrix.sync.aligned.m8n8.x4.shared.b16 {%0,%1,%2,%3}, [%4];"
                 : "=r"(r0), "=r"(r1), "=r"(r2), "=r"(r3) : "r"(addr));
}
__device__ __forceinline__ void mma_bf16(float* c,
                                         uint32_t a0, uint32_t a1, uint32_t a2, uint32_t a3,
                                         uint32_t b0, uint32_t b1) {
    asm volatile("mma.sync.aligned.m16n8k16.row.col.f32.bf16.bf16.f32 "
                 "{%0,%1,%2,%3}, {%4,%5,%6,%7}, {%8,%9}, {%0,%1,%2,%3};"
                 : "+f"(c[0]), "+f"(c[1]), "+f"(c[2]), "+f"(c[3])
                 : "r"(a0), "r"(a1), "r"(a2), "r"(a3), "r"(b0), "r"(b1));
}

// lane-specific ldmatrix.x4 address into a [rows x 64 bf16] SW128 plane
__device__ __forceinline__ uint32_t lds_addr(uint32_t base, int rowbase, int kc, int lane) {
    const int quad = lane >> 3, r8 = lane & 7;
    const int row = rowbase + r8 + (quad & 1) * 8;
    const int kb = kc * 32 + (quad >> 1) * 16;
    return base + row * 128 + (kb ^ ((row & 7) << 4));
}

// ---- bf16 hi/lo split helpers ------------------------------------------------
__device__ __forceinline__ uint32_t pack_bf2(float x, float y) {
    __nv_bfloat162 h = __floats2bfloat162_rn(x, y);
    return *reinterpret_cast<uint32_t*>(&h);
}
__device__ __forceinline__ float2 unpack_bf2(uint32_t u) {
    __nv_bfloat162 h = *reinterpret_cast<__nv_bfloat162*>(&u);
    return __bfloat1622float2(h);
}
__device__ __forceinline__ void stage_pair(char* hip, char* lop, float v) {
    __nv_bfloat16 h = __float2bfloat16_rn(v);
    float r = v - __bfloat162float(h);
    __nv_bfloat16 l = __float2bfloat16_rn(r);
    *reinterpret_cast<__nv_bfloat16*>(hip) = h;
    *reinterpret_cast<__nv_bfloat16*>(lop) = l;
}
__device__ __forceinline__ void split2(float x, float y, uint32_t& hi, uint32_t& lo) {
    hi = pack_bf2(x, y);
    const float2 f = unpack_bf2(hi);
    lo = pack_bf2(x - f.x, y - f.y);
}

// ---- edge kernel config ------------------------------------------------------
constexpr int TILE_E   = 288;               // edges per tile (18 warps x 16)
constexpr int NTHREADS = 576;

// smem byte offsets
constexpr int OFF_SIDX = 0;                 // 288 ints (dst nodes)
constexpr int OFF_D2   = 1152;              // 288 f32
constexpr int OFF_REL  = 2304;              // 576 f32 -> ends 4608
constexpr int OFF_B1   = 4608;              // 64 f32 each below
constexpr int OFF_B2   = 4864;
constexpr int OFF_BP1  = 5120;
constexpr int OFF_W1C  = 5376;              // W_msg1 row 128 (d2 rank-1)
constexpr int OFF_WP2  = 5632;
constexpr int OFF_BP2  = 5888;
// weight B-tiles [n=64][k=64] bf16 SW128 (8KB each), 128B-aligned
constexpr int OFF_B1A_HI = 6144;
constexpr int OFF_B1A_LO = 14336;
constexpr int OFF_B1B_HI = 22528;
constexpr int OFF_B1B_LO = 30720;
constexpr int OFF_B2_HI  = 38912;
constexpr int OFF_B2_LO  = 47104;
constexpr int OFF_BP1_HI = 55296;
constexpr int OFF_BP1_LO = 63488;
// A-tiles [288 x 64] bf16 SW128 (36864 B each)
constexpr int OFF_ADST_HI = 71680;
constexpr int OFF_ADST_LO = 108544;
constexpr int OFF_ASRC_HI = 145408;
constexpr int OFF_ASRC_LO = 182272;
constexpr int EDGE_SMEM_BYTES = 219136;     // 214 KB

// ---- node kernel smem layout (floats) ----------------------------------------
constexpr int NS_WH1 = 0;
constexpr int NS_WH2 = 8192;
constexpr int NS_BH1 = 12288;
constexpr int NS_BH2 = 12352;
constexpr int NS_X   = 12416;
constexpr int NS_Y   = 12928;
constexpr int NODE_SMEM_BYTES = (NS_Y + 256) * 4;

// ---------------------------------------------------------------------------
// 3-term GEMM over K=64, A from smem plane (GEMM1 halves).
// ---------------------------------------------------------------------------
__device__ __forceinline__ void gemm_smemA(
    float acc[8][4],
    uint32_t aHi, uint32_t aLo, uint32_t bHi, uint32_t bLo,
    int rowbase, int lane)
{
#pragma unroll
    for (int kc = 0; kc < 4; ++kc) {
        uint32_t ah[4], al[4];
        ldsm_x4(ah[0], ah[1], ah[2], ah[3], lds_addr(aHi, rowbase, kc, lane));
        ldsm_x4(al[0], al[1], al[2], al[3], lds_addr(aLo, rowbase, kc, lane));
#pragma unroll
        for (int p = 0; p < 4; ++p) {
            uint32_t bh[4], bl[4];
            ldsm_x4(bh[0], bh[1], bh[2], bh[3], lds_addr(bHi, 16 * p, kc, lane));
            ldsm_x4(bl[0], bl[1], bl[2], bl[3], lds_addr(bLo, 16 * p, kc, lane));
#pragma unroll
            for (int o = 0; o < 2; ++o) {
                const int nt = 2 * p + o;
                mma_bf16(acc[nt], ah[0], ah[1], ah[2], ah[3], bh[o], bh[2 + o]);
                mma_bf16(acc[nt], ah[0], ah[1], ah[2], ah[3], bl[o], bl[2 + o]);
                mma_bf16(acc[nt], al[0], al[1], al[2], al[3], bh[o], bh[2 + o]);
            }
        }
    }
}

// 3-term GEMM over K=64, A from registers (16 hi + 16 lo frags).
__device__ __forceinline__ void gemm_regA(
    float acc[8][4],
    const uint32_t afh[16], const uint32_t afl[16],
    uint32_t bHi, uint32_t bLo, int lane)
{
#pragma unroll
    for (int kc = 0; kc < 4; ++kc) {
        const uint32_t* ah = afh + 4 * kc;
        const uint32_t* al = afl + 4 * kc;
#pragma unroll
        for (int p = 0; p < 4; ++p) {
            uint32_t bh[4], bl[4];
            ldsm_x4(bh[0], bh[1], bh[2], bh[3], lds_addr(bHi, 16 * p, kc, lane));
            ldsm_x4(bl[0], bl[1], bl[2], bl[3], lds_addr(bLo, 16 * p, kc, lane));
#pragma unroll
            for (int o = 0; o < 2; ++o) {
                const int nt = 2 * p + o;
                mma_bf16(acc[nt], ah[0], ah[1], ah[2], ah[3], bh[o], bh[2 + o]);
                mma_bf16(acc[nt], ah[0], ah[1], ah[2], ah[3], bl[o], bl[2 + o]);
                mma_bf16(acc[nt], al[0], al[1], al[2], al[3], bh[o], bh[2 + o]);
            }
        }
    }
}

// Convert activation values (accumulator layout) into next-GEMM A-fragments.
__device__ __forceinline__ void make_afrag(
    const float v[8][4], uint32_t afh[16], uint32_t afl[16])
{
#pragma unroll
    for (int kk = 0; kk < 4; ++kk) {
        split2(v[2*kk][0],   v[2*kk][1],   afh[4*kk + 0], afl[4*kk + 0]);
        split2(v[2*kk][2],   v[2*kk][3],   afh[4*kk + 1], afl[4*kk + 1]);
        split2(v[2*kk+1][0], v[2*kk+1][1], afh[4*kk + 2], afl[4*kk + 2]);
        split2(v[2*kk+1][2], v[2*kk+1][3], afh[4*kk + 3], afl[4*kk + 3]);
    }
}

// acc init with bias (rows r0/r1 share bias per column pair)
__device__ __forceinline__ void acc_init_bias(float acc[8][4], const float* sb, int l4) {
#pragma unroll
    for (int nt = 0; nt < 8; ++nt) {
        const int cb = nt * 8 + 2 * l4;
        const float b0 = sb[cb], b1 = sb[cb + 1];
        acc[nt][0] = b0; acc[nt][1] = b1;
        acc[nt][2] = b0; acc[nt][3] = b1;
    }
}

// ---------------------------------------------------------------------------
// Kernel 0a/0b: edge_index dtype detect + normalize.
// ---------------------------------------------------------------------------
__global__ void egnn_detect_kernel(const long long* __restrict__ ei, const int E)
{
    __shared__ int bad;
    if (threadIdx.x == 0) bad = 0;
    __syncthreads();
    const int cnt = E < 1024 ? E : 1024;
    for (int i = threadIdx.x; i < cnt; i += blockDim.x) {
        const long long v = ei[i];
        if (v < 0 || v > 0x7FFFFFFFLL) bad = 1;
    }
    __syncthreads();
    if (threadIdx.x == 0) d_e32flag = bad;
}

__global__ void egnn_cvt_kernel(const void* __restrict__ ei, const int E)
{
    const int i = blockIdx.x * blockDim.x + threadIdx.x;
    if (i >= 2 * E) return;
    int v;
    if (d_e32flag) v = ((const int*)ei)[i];
    else           v = (int)(((const long long*)ei)[i]);
    if (i < E) d_src[i] = v;
    else       d_dst[i - E] = v;
}

// ---------------------------------------------------------------------------
// Kernel 1: hsum = h + h_init; bf16 hi/lo planes; zero accumulators.
// ---------------------------------------------------------------------------
__global__ void egnn_init_kernel(const float* __restrict__ h,
                                 const float* __restrict__ hi, const int N)
{
    const int i = blockIdx.x * blockDim.x + threadIdx.x;
    const int n4 = N * 16;
    if (i < n4) {
        const float4 a = reinterpret_cast<const float4*>(h)[i];
        const float4 b = reinterpret_cast<const float4*>(hi)[i];
        float4 s;
        s.x = a.x + b.x; s.y = a.y + b.y; s.z = a.z + b.z; s.w = a.w + b.w;
        reinterpret_cast<float4*>(d_hsum)[i] = s;
        uint32_t h0, l0, h1, l1;
        split2(s.x, s.y, h0, l0);
        split2(s.z, s.w, h1, l1);
        reinterpret_cast<uint2*>(d_hsum_hi)[i] = make_uint2(h0, h1);
        reinterpret_cast<uint2*>(d_hsum_lo)[i] = make_uint2(l0, l1);
        reinterpret_cast<float4*>(d_agg)[i] = make_float4(0.f, 0.f, 0.f, 0.f);
    }
    if (i < N) d_deg[i] = 0.0f;
    if (i < N * 2) d_posacc[i] = 0.0f;
}

// ---------------------------------------------------------------------------
// Kernel 2: persistent mma.sync edge kernel. 576 threads; 288-edge tiles.
// ---------------------------------------------------------------------------
__global__ void __launch_bounds__(NTHREADS, 1)
egnn_edge_kernel(const float* __restrict__ pos,
                 const float* __restrict__ Wm1, const float* __restrict__ bm1,
                 const float* __restrict__ Wm2, const float* __restrict__ bm2,
                 const float* __restrict__ Wp1, const float* __restrict__ bp1,
                 const float* __restrict__ Wp2, const float* __restrict__ bp2,
                 const int E, const int N)
{
    extern __shared__ char smem[];
    const uint32_t su = smem_to_u32(smem);
    const int tid = threadIdx.x;
    const int wid = tid >> 5;
    const int lane = tid & 31;

    // ---- stage weights as bf16 hi/lo B-tiles (B[n][k] = W[k][n], SW128) ----
    for (int idx = tid; idx < 4096; idx += NTHREADS) {
        const int n = idx >> 6, k = idx & 63;
        const int off = n * 128 + ((k * 2) ^ ((n & 7) << 4));
        stage_pair(smem + OFF_B1A_HI + off, smem + OFF_B1A_LO + off, Wm1[k * 64 + n]);
        stage_pair(smem + OFF_B1B_HI + off, smem + OFF_B1B_LO + off, Wm1[(64 + k) * 64 + n]);
        stage_pair(smem + OFF_B2_HI  + off, smem + OFF_B2_LO  + off, Wm2[k * 64 + n]);
        stage_pair(smem + OFF_BP1_HI + off, smem + OFF_BP1_LO + off, Wp1[k * 64 + n]);
    }
    if (tid < 64) {
        ((float*)(smem + OFF_B1 ))[tid] = bm1[tid];
        ((float*)(smem + OFF_B2 ))[tid] = bm2[tid];
        ((float*)(smem + OFF_BP1))[tid] = bp1[tid];
        ((float*)(smem + OFF_W1C))[tid] = Wm1[128 * 64 + tid];
        ((float*)(smem + OFF_WP2))[tid] = Wp2[tid];
    }
    if (tid == 0) ((float*)(smem + OFF_BP2))[0] = bp2[0];
    __syncthreads();

    int* sidx   = (int*)(smem + OFF_SIDX);   // dst nodes [0..287]
    float* sd2  = (float*)(smem + OFF_D2);
    float* srel = (float*)(smem + OFF_REL);
    const float* sb1  = (const float*)(smem + OFF_B1);
    const float* sb2  = (const float*)(smem + OFF_B2);
    const float* sbp1 = (const float*)(smem + OFF_BP1);
    const float* sw1c = (const float*)(smem + OFF_W1C);
    const float* swp2 = (const float*)(smem + OFF_WP2);

    const int rowbase = wid * 16;         // this warp's 16 edges within tile
    const int l4 = lane & 3;
    const int rgrp = lane >> 2;
    const int r0 = rowbase + rgrp;
    const int r1 = r0 + 8;

    const int nTiles = (E + TILE_E - 1) / TILE_E;

    for (int t = blockIdx.x; t < nTiles; t += gridDim.x) {
        const int eBase = t * TILE_E;

        // ---- gather phase (coalesced: 8 lanes per 128B bf16 row) ----
        if (tid < TILE_E) {      // indices + rel/d2 (one edge per thread)
            const int e = eBase + tid;
            int dn = -1, sn = -1;
            if (e < E) { dn = d_dst[e]; sn = d_src[e]; }
            if ((unsigned)dn >= (unsigned)N) dn = -1;
            if ((unsigned)sn >= (unsigned)N) sn = -1;
            sidx[tid] = dn;
            float rx = 0.f, ry = 0.f;
            if (dn >= 0 && sn >= 0) {
                const float2 pd = reinterpret_cast<const float2*>(pos)[dn];
                const float2 ps = reinterpret_cast<const float2*>(pos)[sn];
                rx = pd.x - ps.x; ry = pd.y - ps.y;
            }
            srel[2 * tid] = rx; srel[2 * tid + 1] = ry;
            sd2[tid] = rx * rx + ry * ry;
        }
        // 576 rows x 8 chunks x 2 planes; 16 copies per thread.
        // Within a warp: 4 rows x 8 chunks per plane -> 4 wavefronts/instr.
#pragma unroll 2
        for (int i = 0; i < 8; ++i) {
            const int gidx = tid + i * NTHREADS;      // 0..4607
            const int row  = gidx >> 3;               // 0..575
            const int c    = gidx & 7;                // 16B chunk in row
            const bool dstp = (row < TILE_E);
            const int er = dstp ? row : row - TILE_E;
            const int e = eBase + er;
            int node = -1;
            if (e < E) node = dstp ? d_dst[e] : d_src[e];
            if ((unsigned)node >= (unsigned)N) node = -1;
            uint4 vh = make_uint4(0u, 0u, 0u, 0u), vl = vh;
            if (node >= 0) {
                vh = reinterpret_cast<const uint4*>(d_hsum_hi)[node * 8 + c];
                vl = reinterpret_cast<const uint4*>(d_hsum_lo)[node * 8 + c];
            }
            const int boff = er * 128 + ((c * 16) ^ ((er & 7) << 4));
            char* hiT = smem + (dstp ? OFF_ADST_HI : OFF_ASRC_HI);
            char* loT = smem + (dstp ? OFF_ADST_LO : OFF_ASRC_LO);
            *reinterpret_cast<uint4*>(hiT + boff) = vh;
            *reinterpret_cast<uint4*>(loT + boff) = vl;
        }
        __syncthreads();   // planes + sidx + rel/d2 published

        float acc[8][4];
        uint32_t afh[16], afl[16];

        // ===== GEMM1: t1 = silu(m_in @ W1 + d2*w1c + b1) (A from smem) ======
        acc_init_bias(acc, sb1, l4);
        gemm_smemA(acc, su + OFF_ADST_HI, su + OFF_ADST_LO,
                   su + OFF_B1A_HI, su + OFF_B1A_LO, rowbase, lane);
        gemm_smemA(acc, su + OFF_ASRC_HI, su + OFF_ASRC_LO,
                   su + OFF_B1B_HI, su + OFF_B1B_LO, rowbase, lane);

        {   // epilogue 1: d2 rank-1 + silu (bias already in acc)
            const float dd0 = sd2[r0], dd1 = sd2[r1];
#pragma unroll
            for (int nt = 0; nt < 8; ++nt) {
                const int cb = nt * 8 + 2 * l4;
                const float w0 = sw1c[cb], w1 = sw1c[cb + 1];
                acc[nt][0] = silu_f(acc[nt][0] + dd0 * w0);
                acc[nt][1] = silu_f(acc[nt][1] + dd0 * w1);
                acc[nt][2] = silu_f(acc[nt][2] + dd1 * w0);
                acc[nt][3] = silu_f(acc[nt][3] + dd1 * w1);
            }
            make_afrag(acc, afh, afl);
        }

        // ===== GEMM2: m = silu(t1 @ W2 + b2) (A from regs) ===================
        acc_init_bias(acc, sb2, l4);
        gemm_regA(acc, afh, afl, su + OFF_B2_HI, su + OFF_B2_LO, lane);

        {   // epilogue 2: silu (bias in acc), scatter agg, then A-frags
            const int dn0 = sidx[r0], dn1 = sidx[r1];
            float* agg0 = d_agg + (size_t)(dn0 < 0 ? 0 : dn0) * 64;
            float* agg1 = d_agg + (size_t)(dn1 < 0 ? 0 : dn1) * 64;
#pragma unroll
            for (int nt = 0; nt < 8; ++nt) {
                const int cb = nt * 8 + 2 * l4;
                acc[nt][0] = silu_f(acc[nt][0]);
                acc[nt][1] = silu_f(acc[nt][1]);
                acc[nt][2] = silu_f(acc[nt][2]);
                acc[nt][3] = silu_f(acc[nt][3]);
                if (dn0 >= 0) red_add_v2(agg0 + cb, acc[nt][0], acc[nt][1]);
                if (dn1 >= 0) red_add_v2(agg1 + cb, acc[nt][2], acc[nt][3]);
            }
            make_afrag(acc, afh, afl);
        }

        // ===== GEMM3: w = silu(m @ Wp1 + bp1) . Wp2 + bp2 (A from regs) ======
        acc_init_bias(acc, sbp1, l4);
        gemm_regA(acc, afh, afl, su + OFF_BP1_HI, su + OFF_BP1_LO, lane);

        {   // epilogue 3: per-row dot with Wp2, 4-lane reduce, pos scatter
            float p0 = 0.f, p1 = 0.f;
#pragma unroll
            for (int nt = 0; nt < 8; ++nt) {
                const int cb = nt * 8 + 2 * l4;
                const float w0 = swp2[cb], w1 = swp2[cb + 1];
                p0 += silu_f(acc[nt][0]) * w0 + silu_f(acc[nt][1]) * w1;
                p1 += silu_f(acc[nt][2]) * w0 + silu_f(acc[nt][3]) * w1;
            }
            p0 += __shfl_xor_sync(0xFFFFFFFFu, p0, 1);
            p0 += __shfl_xor_sync(0xFFFFFFFFu, p0, 2);
            p1 += __shfl_xor_sync(0xFFFFFFFFu, p1, 1);
            p1 += __shfl_xor_sync(0xFFFFFFFFu, p1, 2);
            if (l4 == 0) {
                const float bp2v = ((const float*)(smem + OFF_BP2))[0];
                const int dn0 = sidx[r0], dn1 = sidx[r1];
                if (dn0 >= 0) {
                    const float w = p0 + bp2v;
                    red_add_v2(&d_posacc[dn0 * 2], srel[2 * r0] * w, srel[2 * r0 + 1] * w);
                    atomicAdd(&d_deg[dn0], 1.0f);
                }
                if (dn1 >= 0) {
                    const float w = p1 + bp2v;
                    red_add_v2(&d_posacc[dn1 * 2], srel[2 * r1] * w, srel[2 * r1 + 1] * w);
                    atomicAdd(&d_deg[dn1], 1.0f);
                }
            }
        }
        __syncthreads();   // all warps done with planes/sidx/rel before next tile
    }
}

// ---------------------------------------------------------------------------
// Kernel 3: node update (phi_h) + skip connections + pos update. Warp/node.
// ---------------------------------------------------------------------------
__global__ void __launch_bounds__(128, 4)
egnn_node_kernel(const float* __restrict__ pos,
                 const float* __restrict__ Wh1, const float* __restrict__ bh1,
                 const float* __restrict__ Wh2, const float* __restrict__ bh2,
                 float* __restrict__ out, const int N)
{
    extern __shared__ float sm[];
    const int tid = threadIdx.x;

    for (int i = tid; i < 8192; i += 128) sm[NS_WH1 + i] = Wh1[i];
    for (int i = tid; i < 4096; i += 128) sm[NS_WH2 + i] = Wh2[i];
    if (tid < 64) {
        sm[NS_BH1 + tid] = bh1[tid];
        sm[NS_BH2 + tid] = bh2[tid];
    }
    __syncthreads();

    const int w = tid >> 5, lane = tid & 31;
    float* sx = sm + NS_X + w * 128;
    float* sy = sm + NS_Y + w * 64;
    const float bb10 = sm[NS_BH1 + 2 * lane], bb11 = sm[NS_BH1 + 2 * lane + 1];
    const float bb20 = sm[NS_BH2 + 2 * lane], bb21 = sm[NS_BH2 + 2 * lane + 1];

    const int gw = blockIdx.x * 4 + w;
    const int nw = gridDim.x * 4;
    float* out_pos = out + (long long)N * 64;

    for (int n = gw; n < N; n += nw) {
        sx[lane]      = d_hsum[n * 64 + lane];
        sx[32 + lane] = d_hsum[n * 64 + 32 + lane];
        sx[64 + lane] = d_agg[n * 64 + lane];
        sx[96 + lane] = d_agg[n * 64 + 32 + lane];
        __syncwarp();

        ull acc = 0ULL;
#pragma unroll 4
        for (int i = 0; i < 128; ++i) {
            const float a = sx[i];
            const ull b = reinterpret_cast<const ull*>(sm + NS_WH1 + i * 64)[lane];
            acc = fma2(pk2(a, a), b, acc);
        }
        float y0, y1;
        upk2(acc, y0, y1);
        y0 = silu_f(y0 + bb10);
        y1 = silu_f(y1 + bb11);
        *reinterpret_cast<float2*>(sy + 2 * lane) = make_float2(y0, y1);
        __syncwarp();

        acc = 0ULL;
#pragma unroll 4
        for (int i = 0; i < 64; ++i) {
            const float a = sy[i];
            const ull b = reinterpret_cast<const ull*>(sm + NS_WH2 + i * 64)[lane];
            acc = fma2(pk2(a, a), b, acc);
        }
        float o0, o1;
        upk2(acc, o0, o1);
        o0 += bb20 + sx[2 * lane];
        o1 += bb21 + sx[2 * lane + 1];
        *reinterpret_cast<float2*>(out + (long long)n * 64 + 2 * lane) = make_float2(o0, o1);

        if (lane < 2) {
            const float dg = fmaxf(d_deg[n], 1.0f);
            out_pos[n * 2 + lane] = pos[n * 2 + lane] + d_posacc[n * 2 + lane] / dg;
        }
        __syncwarp();
    }
}

// ---------------------------------------------------------------------------
extern "C" void kernel_launch(void* const* d_in, const int* in_sizes, int n_in,
                              void* d_out, int out_size)
{
    const float* h      = (const float*)d_in[0];
    const float* pos    = (const float*)d_in[1];
    const float* h_init = (const float*)d_in[2];
    const float* Wm1    = (const float*)d_in[3];
    const float* bm1    = (const float*)d_in[4];
    const float* Wm2    = (const float*)d_in[5];
    const float* bm2    = (const float*)d_in[6];
    const float* Wp1    = (const float*)d_in[7];
    const float* bp1    = (const float*)d_in[8];
    const float* Wp2    = (const float*)d_in[9];
    const float* bp2    = (const float*)d_in[10];
    const float* Wh1    = (const float*)d_in[11];
    const float* bh1    = (const float*)d_in[12];
    const float* Wh2    = (const float*)d_in[13];
    const float* bh2    = (const float*)d_in[14];
    const void*  ei     = d_in[15];

    const int N = in_sizes[0] / 64;
    const int E = in_sizes[15] / 2;
    float* out = (float*)d_out;

    cudaFuncSetAttribute(egnn_edge_kernel,
                         cudaFuncAttributeMaxDynamicSharedMemorySize, EDGE_SMEM_BYTES);
    cudaFuncSetAttribute(egnn_node_kernel,
                         cudaFuncAttributeMaxDynamicSharedMemorySize, NODE_SMEM_BYTES);

    egnn_detect_kernel<<<1, 256>>>((const long long*)ei, E);
    egnn_cvt_kernel<<<(2 * E + 255) / 256, 256>>>(ei, E);
    egnn_init_kernel<<<(N * 16 + 255) / 256, 256>>>(h, h_init, N);

    const int nTiles = (E + TILE_E - 1) / TILE_E;
    int eblocks = nTiles < 148 ? nTiles : 148;
    egnn_edge_kernel<<<eblocks, NTHREADS, EDGE_SMEM_BYTES>>>(
        pos, Wm1, bm1, Wm2, bm2, Wp1, bp1, Wp2, bp2, E, N);

    egnn_node_kernel<<<592, 128, NODE_SMEM_BYTES>>>(pos, Wh1, bh1, Wh2, bh2, out, N);
}

// round 15
// speedup vs baseline: 1.5364x; 1.5364x over previous
#include <cuda_runtime.h>
#include <cuda_bf16.h>
#include <stdint.h>

// ---------------------------------------------------------------------------
// EGNN / SpatialNCA step.  N=50000 nodes, D=64, E=800000 edges, P=2.
//
// R15: plain-bf16 edge GEMMs (1-term). Error analysis: edge-GEMM relative
// error ~2^-9 is damped ~180x by the 0.02-scale output MLPs (measured:
// 3-term residual 3.8e-6 -> final 2.1e-8), so bf16 predicts final ~1e-5,
// 100x under the 1e-3 gate. Cuts MMAs 3x, LDSM ~2x, gather bytes 2x.
// Freed smem spent on occupancy: TILE_E=384, 768 threads / 24 warps.
// ---------------------------------------------------------------------------

typedef unsigned long long ull;

#define MAXN 50000
#define MAXD 64
#define MAXE 800000

// scratch (device globals: allocation-free rule)
__device__ __align__(16) float d_hsum[MAXN * MAXD];
__device__ __align__(16) __nv_bfloat16 d_hsum_hi[MAXN * MAXD];
__device__ __align__(16) float d_agg[MAXN * MAXD];
__device__ __align__(16) float d_posacc[MAXN * 2];
__device__ float d_deg[MAXN];
__device__ int   d_src[MAXE];
__device__ int   d_dst[MAXE];
__device__ int   d_e32flag;   // 1 if edge_index buffer is int32, 0 if int64

// ---- small helpers ----------------------------------------------------------
__device__ __forceinline__ uint32_t smem_to_u32(const void* p) {
    uint32_t a;
    asm("{ .reg .u64 t; cvta.to.shared.u64 t, %1; cvt.u32.u64 %0, t; }"
        : "=r"(a) : "l"(p));
    return a;
}
__device__ __forceinline__ float silu_f(float x) {
    return x / (1.0f + __expf(-x));
}
__device__ __forceinline__ void red_add_v2(float* p, float x, float y) {
    asm volatile("red.global.add.v2.f32 [%0], {%1, %2};"
                 :: "l"(p), "f"(x), "f"(y) : "memory");
}
__device__ __forceinline__ ull pk2(float lo, float hi) {
    ull r; asm("mov.b64 %0, {%1,%2};" : "=l"(r) : "f"(lo), "f"(hi)); return r;
}
__device__ __forceinline__ void upk2(ull v, float& lo, float& hi) {
    asm("mov.b64 {%0,%1}, %2;" : "=f"(lo), "=f"(hi) : "l"(v));
}
__device__ __forceinline__ ull fma2(ull a, ull b, ull c) {
    ull d; asm("fma.rn.f32x2 %0, %1, %2, %3;" : "=l"(d) : "l"(a), "l"(b), "l"(c));
    return d;
}

// ---- mma / ldmatrix primitives (sm_80-compatible, run on sm_100 HMMA) -------
__device__ __forceinline__ void ldsm_x4(uint32_t& r0, uint32_t& r1,
                                        uint32_t& r2, uint32_t& r3, uint32_t addr) {
    asm volatile("ldmatrix.sync.aligned.m8n8.x4.shared.b16 {%0,%1,%2,%3}, [%4];"
                 : "=r"(r0), "=r"(r1), "=r"(r2), "=r"(r3) : "r"(addr));
}
__device__ __forceinline__ void mma_bf16(float* c,
                                         uint32_t a0, uint32_t a1, uint32_t a2, uint32_t a3,
                                         uint32_t b0, uint32_t b1) {
    asm volatile("mma.sync.aligned.m16n8k16.row.col.f32.bf16.bf16.f32 "
                 "{%0,%1,%2,%3}, {%4,%5,%6,%7}, {%8,%9}, {%0,%1,%2,%3};"
                 : "+f"(c[0]), "+f"(c[1]), "+f"(c[2]), "+f"(c[3])
                 : "r"(a0), "r"(a1), "r"(a2), "r"(a3), "r"(b0), "r"(b1));
}

// lane-specific ldmatrix.x4 address into a [rows x 64 bf16] SW128 plane
__device__ __forceinline__ uint32_t lds_addr(uint32_t base, int rowbase, int kc, int lane) {
    const int quad = lane >> 3, r8 = lane & 7;
    const int row = rowbase + r8 + (quad & 1) * 8;
    const int kb = kc * 32 + (quad >> 1) * 16;
    return base + row * 128 + (kb ^ ((row & 7) << 4));
}

// ---- bf16 pack helpers --------------------------------------------------------
__device__ __forceinline__ uint32_t pack_bf2(float x, float y) {
    __nv_bfloat162 h = __floats2bfloat162_rn(x, y);
    return *reinterpret_cast<uint32_t*>(&h);
}

// ---- edge kernel config ------------------------------------------------------
constexpr int TILE_E   = 384;               // edges per tile (24 warps x 16)
constexpr int NTHREADS = 768;

// smem byte offsets
constexpr int OFF_SIDX = 0;                 // 384 ints
constexpr int OFF_D2   = 1536;              // 384 f32
constexpr int OFF_REL  = 3072;              // 768 f32 -> 6144
constexpr int OFF_B1   = 6144;              // 64 f32 each below
constexpr int OFF_B2   = 6400;
constexpr int OFF_BP1  = 6656;
constexpr int OFF_W1C  = 6912;              // W_msg1 row 128 (d2 rank-1)
constexpr int OFF_WP2  = 7168;
constexpr int OFF_BP2  = 7424;
// weight B-tiles [n=64][k=64] bf16 SW128 (8KB each)
constexpr int OFF_B1A = 8192;
constexpr int OFF_B1B = 16384;
constexpr int OFF_B2W = 24576;
constexpr int OFF_BP1W = 32768;
// A-tiles [384 x 64] bf16 SW128 (49152 B each)
constexpr int OFF_ADST = 40960;
constexpr int OFF_ASRC = 90112;
constexpr int EDGE_SMEM_BYTES = 139264;     // 136 KB

// ---- node kernel smem layout (floats) ----------------------------------------
constexpr int NS_WH1 = 0;
constexpr int NS_WH2 = 8192;
constexpr int NS_BH1 = 12288;
constexpr int NS_BH2 = 12352;
constexpr int NS_X   = 12416;
constexpr int NS_Y   = 12928;
constexpr int NODE_SMEM_BYTES = (NS_Y + 256) * 4;

// ---------------------------------------------------------------------------
// bf16 GEMM over K=64, A from smem plane.
// ---------------------------------------------------------------------------
__device__ __forceinline__ void gemm_smemA(
    float acc[8][4], uint32_t aP, uint32_t bP, int rowbase, int lane)
{
#pragma unroll
    for (int kc = 0; kc < 4; ++kc) {
        uint32_t ah[4];
        ldsm_x4(ah[0], ah[1], ah[2], ah[3], lds_addr(aP, rowbase, kc, lane));
#pragma unroll
        for (int p = 0; p < 4; ++p) {
            uint32_t bh[4];
            ldsm_x4(bh[0], bh[1], bh[2], bh[3], lds_addr(bP, 16 * p, kc, lane));
            mma_bf16(acc[2 * p],     ah[0], ah[1], ah[2], ah[3], bh[0], bh[2]);
            mma_bf16(acc[2 * p + 1], ah[0], ah[1], ah[2], ah[3], bh[1], bh[3]);
        }
    }
}

// bf16 GEMM over K=64, A from registers (16 frags).
__device__ __forceinline__ void gemm_regA(
    float acc[8][4], const uint32_t af[16], uint32_t bP, int lane)
{
#pragma unroll
    for (int kc = 0; kc < 4; ++kc) {
        const uint32_t* ah = af + 4 * kc;
#pragma unroll
        for (int p = 0; p < 4; ++p) {
            uint32_t bh[4];
            ldsm_x4(bh[0], bh[1], bh[2], bh[3], lds_addr(bP, 16 * p, kc, lane));
            mma_bf16(acc[2 * p],     ah[0], ah[1], ah[2], ah[3], bh[0], bh[2]);
            mma_bf16(acc[2 * p + 1], ah[0], ah[1], ah[2], ah[3], bh[1], bh[3]);
        }
    }
}

// Convert activation values (accumulator layout) into next-GEMM A-fragments.
__device__ __forceinline__ void make_afrag(const float v[8][4], uint32_t af[16])
{
#pragma unroll
    for (int kk = 0; kk < 4; ++kk) {
        af[4*kk + 0] = pack_bf2(v[2*kk][0],   v[2*kk][1]);
        af[4*kk + 1] = pack_bf2(v[2*kk][2],   v[2*kk][3]);
        af[4*kk + 2] = pack_bf2(v[2*kk+1][0], v[2*kk+1][1]);
        af[4*kk + 3] = pack_bf2(v[2*kk+1][2], v[2*kk+1][3]);
    }
}

// acc init with bias (rows r0/r1 share bias per column pair)
__device__ __forceinline__ void acc_init_bias(float acc[8][4], const float* sb, int l4) {
#pragma unroll
    for (int nt = 0; nt < 8; ++nt) {
        const int cb = nt * 8 + 2 * l4;
        const float b0 = sb[cb], b1 = sb[cb + 1];
        acc[nt][0] = b0; acc[nt][1] = b1;
        acc[nt][2] = b0; acc[nt][3] = b1;
    }
}

// ---------------------------------------------------------------------------
// Kernel 0a/0b: edge_index dtype detect + normalize.
// ---------------------------------------------------------------------------
__global__ void egnn_detect_kernel(const long long* __restrict__ ei, const int E)
{
    __shared__ int bad;
    if (threadIdx.x == 0) bad = 0;
    __syncthreads();
    const int cnt = E < 1024 ? E : 1024;
    for (int i = threadIdx.x; i < cnt; i += blockDim.x) {
        const long long v = ei[i];
        if (v < 0 || v > 0x7FFFFFFFLL) bad = 1;
    }
    __syncthreads();
    if (threadIdx.x == 0) d_e32flag = bad;
}

__global__ void egnn_cvt_kernel(const void* __restrict__ ei, const int E)
{
    const int i = blockIdx.x * blockDim.x + threadIdx.x;
    if (i >= 2 * E) return;
    int v;
    if (d_e32flag) v = ((const int*)ei)[i];
    else           v = (int)(((const long long*)ei)[i]);
    if (i < E) d_src[i] = v;
    else       d_dst[i - E] = v;
}

// ---------------------------------------------------------------------------
// Kernel 1: hsum = h + h_init; bf16 plane; zero accumulators.
// ---------------------------------------------------------------------------
__global__ void egnn_init_kernel(const float* __restrict__ h,
                                 const float* __restrict__ hi, const int N)
{
    const int i = blockIdx.x * blockDim.x + threadIdx.x;
    const int n4 = N * 16;
    if (i < n4) {
        const float4 a = reinterpret_cast<const float4*>(h)[i];
        const float4 b = reinterpret_cast<const float4*>(hi)[i];
        float4 s;
        s.x = a.x + b.x; s.y = a.y + b.y; s.z = a.z + b.z; s.w = a.w + b.w;
        reinterpret_cast<float4*>(d_hsum)[i] = s;
        reinterpret_cast<uint2*>(d_hsum_hi)[i] =
            make_uint2(pack_bf2(s.x, s.y), pack_bf2(s.z, s.w));
        reinterpret_cast<float4*>(d_agg)[i] = make_float4(0.f, 0.f, 0.f, 0.f);
    }
    if (i < N) d_deg[i] = 0.0f;
    if (i < N * 2) d_posacc[i] = 0.0f;
}

// ---------------------------------------------------------------------------
// Kernel 2: persistent mma.sync edge kernel. 768 threads; 384-edge tiles.
// ---------------------------------------------------------------------------
__global__ void __launch_bounds__(NTHREADS, 1)
egnn_edge_kernel(const float* __restrict__ pos,
                 const float* __restrict__ Wm1, const float* __restrict__ bm1,
                 const float* __restrict__ Wm2, const float* __restrict__ bm2,
                 const float* __restrict__ Wp1, const float* __restrict__ bp1,
                 const float* __restrict__ Wp2, const float* __restrict__ bp2,
                 const int E, const int N)
{
    extern __shared__ char smem[];
    const uint32_t su = smem_to_u32(smem);
    const int tid = threadIdx.x;
    const int wid = tid >> 5;
    const int lane = tid & 31;

    // ---- stage weights as bf16 B-tiles (B[n][k] = W[k][n], SW128) ----
    for (int idx = tid; idx < 4096; idx += NTHREADS) {
        const int n = idx >> 6, k = idx & 63;
        const int off = n * 128 + ((k * 2) ^ ((n & 7) << 4));
        *reinterpret_cast<__nv_bfloat16*>(smem + OFF_B1A + off) =
            __float2bfloat16_rn(Wm1[k * 64 + n]);
        *reinterpret_cast<__nv_bfloat16*>(smem + OFF_B1B + off) =
            __float2bfloat16_rn(Wm1[(64 + k) * 64 + n]);
        *reinterpret_cast<__nv_bfloat16*>(smem + OFF_B2W + off) =
            __float2bfloat16_rn(Wm2[k * 64 + n]);
        *reinterpret_cast<__nv_bfloat16*>(smem + OFF_BP1W + off) =
            __float2bfloat16_rn(Wp1[k * 64 + n]);
    }
    if (tid < 64) {
        ((float*)(smem + OFF_B1 ))[tid] = bm1[tid];
        ((float*)(smem + OFF_B2 ))[tid] = bm2[tid];
        ((float*)(smem + OFF_BP1))[tid] = bp1[tid];
        ((float*)(smem + OFF_W1C))[tid] = Wm1[128 * 64 + tid];
        ((float*)(smem + OFF_WP2))[tid] = Wp2[tid];
    }
    if (tid == 0) ((float*)(smem + OFF_BP2))[0] = bp2[0];
    __syncthreads();

    int* sidx   = (int*)(smem + OFF_SIDX);   // dst nodes [0..TILE_E)
    float* sd2  = (float*)(smem + OFF_D2);
    float* srel = (float*)(smem + OFF_REL);
    const float* sb1  = (const float*)(smem + OFF_B1);
    const float* sb2  = (const float*)(smem + OFF_B2);
    const float* sbp1 = (const float*)(smem + OFF_BP1);
    const float* sw1c = (const float*)(smem + OFF_W1C);
    const float* swp2 = (const float*)(smem + OFF_WP2);

    const int rowbase = wid * 16;         // this warp's 16 edges within tile
    const int l4 = lane & 3;
    const int rgrp = lane >> 2;
    const int r0 = rowbase + rgrp;
    const int r1 = r0 + 8;

    const int nTiles = (E + TILE_E - 1) / TILE_E;

    for (int t = blockIdx.x; t < nTiles; t += gridDim.x) {
        const int eBase = t * TILE_E;

        // ---- gather phase (coalesced: 8 lanes per 128B bf16 row) ----
        if (tid < TILE_E) {      // indices + rel/d2 (one edge per thread)
            const int e = eBase + tid;
            int dn = -1, sn = -1;
            if (e < E) { dn = d_dst[e]; sn = d_src[e]; }
            if ((unsigned)dn >= (unsigned)N) dn = -1;
            if ((unsigned)sn >= (unsigned)N) sn = -1;
            sidx[tid] = dn;
            float rx = 0.f, ry = 0.f;
            if (dn >= 0 && sn >= 0) {
                const float2 pd = reinterpret_cast<const float2*>(pos)[dn];
                const float2 ps = reinterpret_cast<const float2*>(pos)[sn];
                rx = pd.x - ps.x; ry = pd.y - ps.y;
            }
            srel[2 * tid] = rx; srel[2 * tid + 1] = ry;
            sd2[tid] = rx * rx + ry * ry;
        }
        // 768 rows x 8 chunks = 6144 16B copies; 8 per thread.
        // Warp covers 4 rows x 8 chunks -> 4 wavefronts/instr.
#pragma unroll
        for (int i = 0; i < 8; ++i) {
            const int gidx = tid + i * NTHREADS;      // 0..6143
            const int row  = gidx >> 3;               // 0..767
            const int c    = gidx & 7;                // 16B chunk in row
            const bool dstp = (row < TILE_E);
            const int er = dstp ? row : row - TILE_E;
            const int e = eBase + er;
            int node = -1;
            if (e < E) node = dstp ? d_dst[e] : d_src[e];
            if ((unsigned)node >= (unsigned)N) node = -1;
            uint4 vh = make_uint4(0u, 0u, 0u, 0u);
            if (node >= 0)
                vh = reinterpret_cast<const uint4*>(d_hsum_hi)[node * 8 + c];
            const int boff = er * 128 + ((c * 16) ^ ((er & 7) << 4));
            char* aT = smem + (dstp ? OFF_ADST : OFF_ASRC);
            *reinterpret_cast<uint4*>(aT + boff) = vh;
        }
        __syncthreads();   // planes + sidx + rel/d2 published

        float acc[8][4];
        uint32_t af[16];

        // ===== GEMM1: t1 = silu(m_in @ W1 + d2*w1c + b1) (A from smem) ======
        acc_init_bias(acc, sb1, l4);
        gemm_smemA(acc, su + OFF_ADST, su + OFF_B1A, rowbase, lane);
        gemm_smemA(acc, su + OFF_ASRC, su + OFF_B1B, rowbase, lane);

        {   // epilogue 1: d2 rank-1 + silu (bias already in acc)
            const float dd0 = sd2[r0], dd1 = sd2[r1];
#pragma unroll
            for (int nt = 0; nt < 8; ++nt) {
                const int cb = nt * 8 + 2 * l4;
                const float w0 = sw1c[cb], w1 = sw1c[cb + 1];
                acc[nt][0] = silu_f(acc[nt][0] + dd0 * w0);
                acc[nt][1] = silu_f(acc[nt][1] + dd0 * w1);
                acc[nt][2] = silu_f(acc[nt][2] + dd1 * w0);
                acc[nt][3] = silu_f(acc[nt][3] + dd1 * w1);
            }
            make_afrag(acc, af);
        }

        // ===== GEMM2: m = silu(t1 @ W2 + b2) (A from regs) ===================
        acc_init_bias(acc, sb2, l4);
        gemm_regA(acc, af, su + OFF_B2W, lane);

        {   // epilogue 2: silu (bias in acc), scatter agg, then A-frags
            const int dn0 = sidx[r0], dn1 = sidx[r1];
            float* agg0 = d_agg + (size_t)(dn0 < 0 ? 0 : dn0) * 64;
            float* agg1 = d_agg + (size_t)(dn1 < 0 ? 0 : dn1) * 64;
#pragma unroll
            for (int nt = 0; nt < 8; ++nt) {
                const int cb = nt * 8 + 2 * l4;
                acc[nt][0] = silu_f(acc[nt][0]);
                acc[nt][1] = silu_f(acc[nt][1]);
                acc[nt][2] = silu_f(acc[nt][2]);
                acc[nt][3] = silu_f(acc[nt][3]);
                if (dn0 >= 0) red_add_v2(agg0 + cb, acc[nt][0], acc[nt][1]);
                if (dn1 >= 0) red_add_v2(agg1 + cb, acc[nt][2], acc[nt][3]);
            }
            make_afrag(acc, af);
        }

        // ===== GEMM3: w = silu(m @ Wp1 + bp1) . Wp2 + bp2 (A from regs) ======
        acc_init_bias(acc, sbp1, l4);
        gemm_regA(acc, af, su + OFF_BP1W, lane);

        {   // epilogue 3: per-row dot with Wp2, 4-lane reduce, pos scatter
            float p0 = 0.f, p1 = 0.f;
#pragma unroll
            for (int nt = 0; nt < 8; ++nt) {
                const int cb = nt * 8 + 2 * l4;
                const float w0 = swp2[cb], w1 = swp2[cb + 1];
                p0 += silu_f(acc[nt][0]) * w0 + silu_f(acc[nt][1]) * w1;
                p1 += silu_f(acc[nt][2]) * w0 + silu_f(acc[nt][3]) * w1;
            }
            p0 += __shfl_xor_sync(0xFFFFFFFFu, p0, 1);
            p0 += __shfl_xor_sync(0xFFFFFFFFu, p0, 2);
            p1 += __shfl_xor_sync(0xFFFFFFFFu, p1, 1);
            p1 += __shfl_xor_sync(0xFFFFFFFFu, p1, 2);
            if (l4 == 0) {
                const float bp2v = ((const float*)(smem + OFF_BP2))[0];
                const int dn0 = sidx[r0], dn1 = sidx[r1];
                if (dn0 >= 0) {
                    const float w = p0 + bp2v;
                    red_add_v2(&d_posacc[dn0 * 2], srel[2 * r0] * w, srel[2 * r0 + 1] * w);
                    atomicAdd(&d_deg[dn0], 1.0f);
                }
                if (dn1 >= 0) {
                    const float w = p1 + bp2v;
                    red_add_v2(&d_posacc[dn1 * 2], srel[2 * r1] * w, srel[2 * r1 + 1] * w);
                    atomicAdd(&d_deg[dn1], 1.0f);
                }
            }
        }
        __syncthreads();   // all warps done with planes/sidx/rel before next tile
    }
}

// ---------------------------------------------------------------------------
// Kernel 3: node update (phi_h) + skip connections + pos update. Warp/node.
// ---------------------------------------------------------------------------
__global__ void __launch_bounds__(128, 4)
egnn_node_kernel(const float* __restrict__ pos,
                 const float* __restrict__ Wh1, const float* __restrict__ bh1,
                 const float* __restrict__ Wh2, const float* __restrict__ bh2,
                 float* __restrict__ out, const int N)
{
    extern __shared__ float sm[];
    const int tid = threadIdx.x;

    for (int i = tid; i < 8192; i += 128) sm[NS_WH1 + i] = Wh1[i];
    for (int i = tid; i < 4096; i += 128) sm[NS_WH2 + i] = Wh2[i];
    if (tid < 64) {
        sm[NS_BH1 + tid] = bh1[tid];
        sm[NS_BH2 + tid] = bh2[tid];
    }
    __syncthreads();

    const int w = tid >> 5, lane = tid & 31;
    float* sx = sm + NS_X + w * 128;
    float* sy = sm + NS_Y + w * 64;
    const float bb10 = sm[NS_BH1 + 2 * lane], bb11 = sm[NS_BH1 + 2 * lane + 1];
    const float bb20 = sm[NS_BH2 + 2 * lane], bb21 = sm[NS_BH2 + 2 * lane + 1];

    const int gw = blockIdx.x * 4 + w;
    const int nw = gridDim.x * 4;
    float* out_pos = out + (long long)N * 64;

    for (int n = gw; n < N; n += nw) {
        sx[lane]      = d_hsum[n * 64 + lane];
        sx[32 + lane] = d_hsum[n * 64 + 32 + lane];
        sx[64 + lane] = d_agg[n * 64 + lane];
        sx[96 + lane] = d_agg[n * 64 + 32 + lane];
        __syncwarp();

        ull acc = 0ULL;
#pragma unroll 4
        for (int i = 0; i < 128; ++i) {
            const float a = sx[i];
            const ull b = reinterpret_cast<const ull*>(sm + NS_WH1 + i * 64)[lane];
            acc = fma2(pk2(a, a), b, acc);
        }
        float y0, y1;
        upk2(acc, y0, y1);
        y0 = silu_f(y0 + bb10);
        y1 = silu_f(y1 + bb11);
        *reinterpret_cast<float2*>(sy + 2 * lane) = make_float2(y0, y1);
        __syncwarp();

        acc = 0ULL;
#pragma unroll 4
        for (int i = 0; i < 64; ++i) {
            const float a = sy[i];
            const ull b = reinterpret_cast<const ull*>(sm + NS_WH2 + i * 64)[lane];
            acc = fma2(pk2(a, a), b, acc);
        }
        float o0, o1;
        upk2(acc, o0, o1);
        o0 += bb20 + sx[2 * lane];
        o1 += bb21 + sx[2 * lane + 1];
        *reinterpret_cast<float2*>(out + (long long)n * 64 + 2 * lane) = make_float2(o0, o1);

        if (lane < 2) {
            const float dg = fmaxf(d_deg[n], 1.0f);
            out_pos[n * 2 + lane] = pos[n * 2 + lane] + d_posacc[n * 2 + lane] / dg;
        }
        __syncwarp();
    }
}

// ---------------------------------------------------------------------------
extern "C" void kernel_launch(void* const* d_in, const int* in_sizes, int n_in,
                              void* d_out, int out_size)
{
    const float* h      = (const float*)d_in[0];
    const float* pos    = (const float*)d_in[1];
    const float* h_init = (const float*)d_in[2];
    const float* Wm1    = (const float*)d_in[3];
    const float* bm1    = (const float*)d_in[4];
    const float* Wm2    = (const float*)d_in[5];
    const float* bm2    = (const float*)d_in[6];
    const float* Wp1    = (const float*)d_in[7];
    const float* bp1    = (const float*)d_in[8];
    const float* Wp2    = (const float*)d_in[9];
    const float* bp2    = (const float*)d_in[10];
    const float* Wh1    = (const float*)d_in[11];
    const float* bh1    = (const float*)d_in[12];
    const float* Wh2    = (const float*)d_in[13];
    const float* bh2    = (const float*)d_in[14];
    const void*  ei     = d_in[15];

    const int N = in_sizes[0] / 64;
    const int E = in_sizes[15] / 2;
    float* out = (float*)d_out;

    cudaFuncSetAttribute(egnn_edge_kernel,
                         cudaFuncAttributeMaxDynamicSharedMemorySize, EDGE_SMEM_BYTES);
    cudaFuncSetAttribute(egnn_node_kernel,
                         cudaFuncAttributeMaxDynamicSharedMemorySize, NODE_SMEM_BYTES);

    egnn_detect_kernel<<<1, 256>>>((const long long*)ei, E);
    egnn_cvt_kernel<<<(2 * E + 255) / 256, 256>>>(ei, E);
    egnn_init_kernel<<<(N * 16 + 255) / 256, 256>>>(h, h_init, N);

    const int nTiles = (E + TILE_E - 1) / TILE_E;
    int eblocks = nTiles < 148 ? nTiles : 148;
    egnn_edge_kernel<<<eblocks, NTHREADS, EDGE_SMEM_BYTES>>>(
        pos, Wm1, bm1, Wm2, bm2, Wp1, bp1, Wp2, bp2, E, N);

    egnn_node_kernel<<<592, 128, NODE_SMEM_BYTES>>>(pos, Wh1, bh1, Wh2, bh2, out, N);
}

// round 16
// speedup vs baseline: 1.9757x; 1.2859x over previous
#include <cuda_runtime.h>
#include <cuda_bf16.h>
#include <stdint.h>

// ---------------------------------------------------------------------------
// EGNN / SpatialNCA step.  N=50000 nodes, D=64, E=800000 edges, P=2.
//
// R16 = R15 (plain-bf16 mma edge GEMMs) +
//  - edge kernel: 2 CTAs/SM (TILE_E=192, 384 threads, 84.5KB smem) for
//    cross-CTA phase overlap at the same 24 warps/SM.
//  - node MLP (phi_h) rewritten on the same bf16 mma pipeline (128-node
//    tiles, GEMM1 smem-A over [h|agg], GEMM2 reg-A, fp32 skip, pos update).
// ---------------------------------------------------------------------------

typedef unsigned long long ull;

#define MAXN 50000
#define MAXD 64
#define MAXE 800000

// scratch (device globals: allocation-free rule)
__device__ __align__(16) float d_hsum[MAXN * MAXD];
__device__ __align__(16) __nv_bfloat16 d_hsum_hi[MAXN * MAXD];
__device__ __align__(16) float d_agg[MAXN * MAXD];
__device__ __align__(16) float d_posacc[MAXN * 2];
__device__ float d_deg[MAXN];
__device__ int   d_src[MAXE];
__device__ int   d_dst[MAXE];
__device__ int   d_e32flag;   // 1 if edge_index buffer is int32, 0 if int64

// ---- small helpers ----------------------------------------------------------
__device__ __forceinline__ uint32_t smem_to_u32(const void* p) {
    uint32_t a;
    asm("{ .reg .u64 t; cvta.to.shared.u64 t, %1; cvt.u32.u64 %0, t; }"
        : "=r"(a) : "l"(p));
    return a;
}
__device__ __forceinline__ float silu_f(float x) {
    return x / (1.0f + __expf(-x));
}
__device__ __forceinline__ void red_add_v2(float* p, float x, float y) {
    asm volatile("red.global.add.v2.f32 [%0], {%1, %2};"
                 :: "l"(p), "f"(x), "f"(y) : "memory");
}

// ---- mma / ldmatrix primitives (sm_80-compatible, run on sm_100 HMMA) -------
__device__ __forceinline__ void ldsm_x4(uint32_t& r0, uint32_t& r1,
                                        uint32_t& r2, uint32_t& r3, uint32_t addr) {
    asm volatile("ldmatrix.sync.aligned.m8n8.x4.shared.b16 {%0,%1,%2,%3}, [%4];"
                 : "=r"(r0), "=r"(r1), "=r"(r2), "=r"(r3) : "r"(addr));
}
__device__ __forceinline__ void mma_bf16(float* c,
                                         uint32_t a0, uint32_t a1, uint32_t a2, uint32_t a3,
                                         uint32_t b0, uint32_t b1) {
    asm volatile("mma.sync.aligned.m16n8k16.row.col.f32.bf16.bf16.f32 "
                 "{%0,%1,%2,%3}, {%4,%5,%6,%7}, {%8,%9}, {%0,%1,%2,%3};"
                 : "+f"(c[0]), "+f"(c[1]), "+f"(c[2]), "+f"(c[3])
                 : "r"(a0), "r"(a1), "r"(a2), "r"(a3), "r"(b0), "r"(b1));
}

// lane-specific ldmatrix.x4 address into a [rows x 64 bf16] SW128 plane
__device__ __forceinline__ uint32_t lds_addr(uint32_t base, int rowbase, int kc, int lane) {
    const int quad = lane >> 3, r8 = lane & 7;
    const int row = rowbase + r8 + (quad & 1) * 8;
    const int kb = kc * 32 + (quad >> 1) * 16;
    return base + row * 128 + (kb ^ ((row & 7) << 4));
}

// ---- bf16 pack helpers --------------------------------------------------------
__device__ __forceinline__ uint32_t pack_bf2(float x, float y) {
    __nv_bfloat162 h = __floats2bfloat162_rn(x, y);
    return *reinterpret_cast<uint32_t*>(&h);
}

// ---- shared GEMM building blocks ---------------------------------------------
__device__ __forceinline__ void gemm_smemA(
    float acc[8][4], uint32_t aP, uint32_t bP, int rowbase, int lane)
{
#pragma unroll
    for (int kc = 0; kc < 4; ++kc) {
        uint32_t ah[4];
        ldsm_x4(ah[0], ah[1], ah[2], ah[3], lds_addr(aP, rowbase, kc, lane));
#pragma unroll
        for (int p = 0; p < 4; ++p) {
            uint32_t bh[4];
            ldsm_x4(bh[0], bh[1], bh[2], bh[3], lds_addr(bP, 16 * p, kc, lane));
            mma_bf16(acc[2 * p],     ah[0], ah[1], ah[2], ah[3], bh[0], bh[2]);
            mma_bf16(acc[2 * p + 1], ah[0], ah[1], ah[2], ah[3], bh[1], bh[3]);
        }
    }
}
__device__ __forceinline__ void gemm_regA(
    float acc[8][4], const uint32_t af[16], uint32_t bP, int lane)
{
#pragma unroll
    for (int kc = 0; kc < 4; ++kc) {
        const uint32_t* ah = af + 4 * kc;
#pragma unroll
        for (int p = 0; p < 4; ++p) {
            uint32_t bh[4];
            ldsm_x4(bh[0], bh[1], bh[2], bh[3], lds_addr(bP, 16 * p, kc, lane));
            mma_bf16(acc[2 * p],     ah[0], ah[1], ah[2], ah[3], bh[0], bh[2]);
            mma_bf16(acc[2 * p + 1], ah[0], ah[1], ah[2], ah[3], bh[1], bh[3]);
        }
    }
}
__device__ __forceinline__ void make_afrag(const float v[8][4], uint32_t af[16])
{
#pragma unroll
    for (int kk = 0; kk < 4; ++kk) {
        af[4*kk + 0] = pack_bf2(v[2*kk][0],   v[2*kk][1]);
        af[4*kk + 1] = pack_bf2(v[2*kk][2],   v[2*kk][3]);
        af[4*kk + 2] = pack_bf2(v[2*kk+1][0], v[2*kk+1][1]);
        af[4*kk + 3] = pack_bf2(v[2*kk+1][2], v[2*kk+1][3]);
    }
}
__device__ __forceinline__ void acc_init_bias(float acc[8][4], const float* sb, int l4) {
#pragma unroll
    for (int nt = 0; nt < 8; ++nt) {
        const int cb = nt * 8 + 2 * l4;
        const float b0 = sb[cb], b1 = sb[cb + 1];
        acc[nt][0] = b0; acc[nt][1] = b1;
        acc[nt][2] = b0; acc[nt][3] = b1;
    }
}

// ---- edge kernel config (2 CTAs/SM) -------------------------------------------
constexpr int TILE_E   = 192;               // edges per tile (12 warps x 16)
constexpr int NTHREADS = 384;

constexpr int OFF_SIDX = 0;                 // 192 ints
constexpr int OFF_D2   = 768;               // 192 f32
constexpr int OFF_REL  = 1536;              // 384 f32 -> 3072
constexpr int OFF_B1   = 3072;
constexpr int OFF_B2   = 3328;
constexpr int OFF_BP1  = 3584;
constexpr int OFF_W1C  = 3840;
constexpr int OFF_WP2  = 4096;
constexpr int OFF_BP2  = 4352;
// weight B-tiles [n=64][k=64] bf16 SW128 (8KB each)
constexpr int OFF_B1A  = 4608;
constexpr int OFF_B1B  = 12800;
constexpr int OFF_B2W  = 20992;
constexpr int OFF_BP1W = 29184;
// A-tiles [192 x 64] bf16 SW128 (24576 B each)
constexpr int OFF_ADST = 37376;
constexpr int OFF_ASRC = 61952;
constexpr int EDGE_SMEM_BYTES = 86528;      // 84.5 KB -> 2 CTAs/SM

// ---- node kernel config (mma) --------------------------------------------------
constexpr int NT_TILE    = 128;             // nodes per tile (8 warps x 16)
constexpr int NT_THREADS = 256;

constexpr int NOFF_WA  = 0;                 // Wh1 k=0..63  B-tile, 8KB
constexpr int NOFF_WB  = 8192;              // Wh1 k=64..127, 8KB
constexpr int NOFF_W2  = 16384;             // Wh2, 8KB
constexpr int NOFF_BH1 = 24576;             // 256B
constexpr int NOFF_BH2 = 24832;             // 256B
constexpr int NOFF_AH  = 25088;             // 128 x 128B = 16384
constexpr int NOFF_AG  = 41472;             // 16384 -> end 57856
constexpr int NODE_SMEM_BYTES = 57856;      // 56.5 KB -> 3 CTAs/SM

// ---------------------------------------------------------------------------
// Kernel 0a/0b: edge_index dtype detect + normalize.
// ---------------------------------------------------------------------------
__global__ void egnn_detect_kernel(const long long* __restrict__ ei, const int E)
{
    __shared__ int bad;
    if (threadIdx.x == 0) bad = 0;
    __syncthreads();
    const int cnt = E < 1024 ? E : 1024;
    for (int i = threadIdx.x; i < cnt; i += blockDim.x) {
        const long long v = ei[i];
        if (v < 0 || v > 0x7FFFFFFFLL) bad = 1;
    }
    __syncthreads();
    if (threadIdx.x == 0) d_e32flag = bad;
}

__global__ void egnn_cvt_kernel(const void* __restrict__ ei, const int E)
{
    const int i = blockIdx.x * blockDim.x + threadIdx.x;
    if (i >= 2 * E) return;
    int v;
    if (d_e32flag) v = ((const int*)ei)[i];
    else           v = (int)(((const long long*)ei)[i]);
    if (i < E) d_src[i] = v;
    else       d_dst[i - E] = v;
}

// ---------------------------------------------------------------------------
// Kernel 1: hsum = h + h_init; bf16 plane; zero accumulators.
// ---------------------------------------------------------------------------
__global__ void egnn_init_kernel(const float* __restrict__ h,
                                 const float* __restrict__ hi, const int N)
{
    const int i = blockIdx.x * blockDim.x + threadIdx.x;
    const int n4 = N * 16;
    if (i < n4) {
        const float4 a = reinterpret_cast<const float4*>(h)[i];
        const float4 b = reinterpret_cast<const float4*>(hi)[i];
        float4 s;
        s.x = a.x + b.x; s.y = a.y + b.y; s.z = a.z + b.z; s.w = a.w + b.w;
        reinterpret_cast<float4*>(d_hsum)[i] = s;
        reinterpret_cast<uint2*>(d_hsum_hi)[i] =
            make_uint2(pack_bf2(s.x, s.y), pack_bf2(s.z, s.w));
        reinterpret_cast<float4*>(d_agg)[i] = make_float4(0.f, 0.f, 0.f, 0.f);
    }
    if (i < N) d_deg[i] = 0.0f;
    if (i < N * 2) d_posacc[i] = 0.0f;
}

// ---------------------------------------------------------------------------
// Kernel 2: persistent mma.sync edge kernel. 384 threads; 192-edge tiles;
// 2 CTAs per SM for cross-CTA phase overlap.
// ---------------------------------------------------------------------------
__global__ void __launch_bounds__(NTHREADS, 2)
egnn_edge_kernel(const float* __restrict__ pos,
                 const float* __restrict__ Wm1, const float* __restrict__ bm1,
                 const float* __restrict__ Wm2, const float* __restrict__ bm2,
                 const float* __restrict__ Wp1, const float* __restrict__ bp1,
                 const float* __restrict__ Wp2, const float* __restrict__ bp2,
                 const int E, const int N)
{
    extern __shared__ char smem[];
    const uint32_t su = smem_to_u32(smem);
    const int tid = threadIdx.x;
    const int wid = tid >> 5;
    const int lane = tid & 31;

    // ---- stage weights as bf16 B-tiles (B[n][k] = W[k][n], SW128) ----
    for (int idx = tid; idx < 4096; idx += NTHREADS) {
        const int n = idx >> 6, k = idx & 63;
        const int off = n * 128 + ((k * 2) ^ ((n & 7) << 4));
        *reinterpret_cast<__nv_bfloat16*>(smem + OFF_B1A + off) =
            __float2bfloat16_rn(Wm1[k * 64 + n]);
        *reinterpret_cast<__nv_bfloat16*>(smem + OFF_B1B + off) =
            __float2bfloat16_rn(Wm1[(64 + k) * 64 + n]);
        *reinterpret_cast<__nv_bfloat16*>(smem + OFF_B2W + off) =
            __float2bfloat16_rn(Wm2[k * 64 + n]);
        *reinterpret_cast<__nv_bfloat16*>(smem + OFF_BP1W + off) =
            __float2bfloat16_rn(Wp1[k * 64 + n]);
    }
    if (tid < 64) {
        ((float*)(smem + OFF_B1 ))[tid] = bm1[tid];
        ((float*)(smem + OFF_B2 ))[tid] = bm2[tid];
        ((float*)(smem + OFF_BP1))[tid] = bp1[tid];
        ((float*)(smem + OFF_W1C))[tid] = Wm1[128 * 64 + tid];
        ((float*)(smem + OFF_WP2))[tid] = Wp2[tid];
    }
    if (tid == 0) ((float*)(smem + OFF_BP2))[0] = bp2[0];
    __syncthreads();

    int* sidx   = (int*)(smem + OFF_SIDX);
    float* sd2  = (float*)(smem + OFF_D2);
    float* srel = (float*)(smem + OFF_REL);
    const float* sb1  = (const float*)(smem + OFF_B1);
    const float* sb2  = (const float*)(smem + OFF_B2);
    const float* sbp1 = (const float*)(smem + OFF_BP1);
    const float* sw1c = (const float*)(smem + OFF_W1C);
    const float* swp2 = (const float*)(smem + OFF_WP2);

    const int rowbase = wid * 16;
    const int l4 = lane & 3;
    const int rgrp = lane >> 2;
    const int r0 = rowbase + rgrp;
    const int r1 = r0 + 8;

    const int nTiles = (E + TILE_E - 1) / TILE_E;

    for (int t = blockIdx.x; t < nTiles; t += gridDim.x) {
        const int eBase = t * TILE_E;

        // ---- gather phase (coalesced: 8 lanes per 128B bf16 row) ----
        if (tid < TILE_E) {
            const int e = eBase + tid;
            int dn = -1, sn = -1;
            if (e < E) { dn = d_dst[e]; sn = d_src[e]; }
            if ((unsigned)dn >= (unsigned)N) dn = -1;
            if ((unsigned)sn >= (unsigned)N) sn = -1;
            sidx[tid] = dn;
            float rx = 0.f, ry = 0.f;
            if (dn >= 0 && sn >= 0) {
                const float2 pd = reinterpret_cast<const float2*>(pos)[dn];
                const float2 ps = reinterpret_cast<const float2*>(pos)[sn];
                rx = pd.x - ps.x; ry = pd.y - ps.y;
            }
            srel[2 * tid] = rx; srel[2 * tid + 1] = ry;
            sd2[tid] = rx * rx + ry * ry;
        }
#pragma unroll
        for (int i = 0; i < 8; ++i) {
            const int gidx = tid + i * NTHREADS;      // 0..3071
            const int row  = gidx >> 3;               // 0..383
            const int c    = gidx & 7;
            const bool dstp = (row < TILE_E);
            const int er = dstp ? row : row - TILE_E;
            const int e = eBase + er;
            int node = -1;
            if (e < E) node = dstp ? d_dst[e] : d_src[e];
            if ((unsigned)node >= (unsigned)N) node = -1;
            uint4 vh = make_uint4(0u, 0u, 0u, 0u);
            if (node >= 0)
                vh = reinterpret_cast<const uint4*>(d_hsum_hi)[node * 8 + c];
            const int boff = er * 128 + ((c * 16) ^ ((er & 7) << 4));
            char* aT = smem + (dstp ? OFF_ADST : OFF_ASRC);
            *reinterpret_cast<uint4*>(aT + boff) = vh;
        }
        __syncthreads();

        float acc[8][4];
        uint32_t af[16];

        // ===== GEMM1 =====
        acc_init_bias(acc, sb1, l4);
        gemm_smemA(acc, su + OFF_ADST, su + OFF_B1A, rowbase, lane);
        gemm_smemA(acc, su + OFF_ASRC, su + OFF_B1B, rowbase, lane);
        {
            const float dd0 = sd2[r0], dd1 = sd2[r1];
#pragma unroll
            for (int nt = 0; nt < 8; ++nt) {
                const int cb = nt * 8 + 2 * l4;
                const float w0 = sw1c[cb], w1 = sw1c[cb + 1];
                acc[nt][0] = silu_f(acc[nt][0] + dd0 * w0);
                acc[nt][1] = silu_f(acc[nt][1] + dd0 * w1);
                acc[nt][2] = silu_f(acc[nt][2] + dd1 * w0);
                acc[nt][3] = silu_f(acc[nt][3] + dd1 * w1);
            }
            make_afrag(acc, af);
        }

        // ===== GEMM2 =====
        acc_init_bias(acc, sb2, l4);
        gemm_regA(acc, af, su + OFF_B2W, lane);
        {
            const int dn0 = sidx[r0], dn1 = sidx[r1];
            float* agg0 = d_agg + (size_t)(dn0 < 0 ? 0 : dn0) * 64;
            float* agg1 = d_agg + (size_t)(dn1 < 0 ? 0 : dn1) * 64;
#pragma unroll
            for (int nt = 0; nt < 8; ++nt) {
                const int cb = nt * 8 + 2 * l4;
                acc[nt][0] = silu_f(acc[nt][0]);
                acc[nt][1] = silu_f(acc[nt][1]);
                acc[nt][2] = silu_f(acc[nt][2]);
                acc[nt][3] = silu_f(acc[nt][3]);
                if (dn0 >= 0) red_add_v2(agg0 + cb, acc[nt][0], acc[nt][1]);
                if (dn1 >= 0) red_add_v2(agg1 + cb, acc[nt][2], acc[nt][3]);
            }
            make_afrag(acc, af);
        }

        // ===== GEMM3 =====
        acc_init_bias(acc, sbp1, l4);
        gemm_regA(acc, af, su + OFF_BP1W, lane);
        {
            float p0 = 0.f, p1 = 0.f;
#pragma unroll
            for (int nt = 0; nt < 8; ++nt) {
                const int cb = nt * 8 + 2 * l4;
                const float w0 = swp2[cb], w1 = swp2[cb + 1];
                p0 += silu_f(acc[nt][0]) * w0 + silu_f(acc[nt][1]) * w1;
                p1 += silu_f(acc[nt][2]) * w0 + silu_f(acc[nt][3]) * w1;
            }
            p0 += __shfl_xor_sync(0xFFFFFFFFu, p0, 1);
            p0 += __shfl_xor_sync(0xFFFFFFFFu, p0, 2);
            p1 += __shfl_xor_sync(0xFFFFFFFFu, p1, 1);
            p1 += __shfl_xor_sync(0xFFFFFFFFu, p1, 2);
            if (l4 == 0) {
                const float bp2v = ((const float*)(smem + OFF_BP2))[0];
                const int dn0 = sidx[r0], dn1 = sidx[r1];
                if (dn0 >= 0) {
                    const float w = p0 + bp2v;
                    red_add_v2(&d_posacc[dn0 * 2], srel[2 * r0] * w, srel[2 * r0 + 1] * w);
                    atomicAdd(&d_deg[dn0], 1.0f);
                }
                if (dn1 >= 0) {
                    const float w = p1 + bp2v;
                    red_add_v2(&d_posacc[dn1 * 2], srel[2 * r1] * w, srel[2 * r1 + 1] * w);
                    atomicAdd(&d_deg[dn1], 1.0f);
                }
            }
        }
        __syncthreads();
    }
}

// ---------------------------------------------------------------------------
// Kernel 3: node update (phi_h) via bf16 mma. 256 threads; 128-node tiles.
// out = hsum + (silu([h|agg] @ Wh1 + bh1) @ Wh2 + bh2); pos update folded in.
// ---------------------------------------------------------------------------
__global__ void __launch_bounds__(NT_THREADS, 3)
egnn_node_kernel(const float* __restrict__ pos,
                 const float* __restrict__ Wh1, const float* __restrict__ bh1,
                 const float* __restrict__ Wh2, const float* __restrict__ bh2,
                 float* __restrict__ out, const int N)
{
    extern __shared__ char smem[];
    const uint32_t su = smem_to_u32(smem);
    const int tid = threadIdx.x;
    const int wid = tid >> 5;
    const int lane = tid & 31;

    // stage weights: B[n][k] = W[k][n], SW128
    for (int idx = tid; idx < 4096; idx += NT_THREADS) {
        const int n = idx >> 6, k = idx & 63;
        const int off = n * 128 + ((k * 2) ^ ((n & 7) << 4));
        *reinterpret_cast<__nv_bfloat16*>(smem + NOFF_WA + off) =
            __float2bfloat16_rn(Wh1[k * 64 + n]);
        *reinterpret_cast<__nv_bfloat16*>(smem + NOFF_WB + off) =
            __float2bfloat16_rn(Wh1[(64 + k) * 64 + n]);
        *reinterpret_cast<__nv_bfloat16*>(smem + NOFF_W2 + off) =
            __float2bfloat16_rn(Wh2[k * 64 + n]);
    }
    if (tid < 64) {
        ((float*)(smem + NOFF_BH1))[tid] = bh1[tid];
        ((float*)(smem + NOFF_BH2))[tid] = bh2[tid];
    }
    __syncthreads();

    const float* sbh1 = (const float*)(smem + NOFF_BH1);
    const float* sbh2 = (const float*)(smem + NOFF_BH2);

    const int base = blockIdx.x * NT_TILE;

    // gather: h rows from bf16 plane (copy), agg rows converted inline
#pragma unroll
    for (int i = 0; i < 4; ++i) {
        const int gidx = tid + i * NT_THREADS;   // 0..1023
        const int row = gidx >> 3, c = gidx & 7;
        const int n = base + row;
        uint4 v = make_uint4(0u, 0u, 0u, 0u);
        if (n < N) v = reinterpret_cast<const uint4*>(d_hsum_hi)[n * 8 + c];
        const int boff = row * 128 + ((c * 16) ^ ((row & 7) << 4));
        *reinterpret_cast<uint4*>(smem + NOFF_AH + boff) = v;
    }
#pragma unroll
    for (int i = 0; i < 4; ++i) {
        const int gidx = tid + i * NT_THREADS;
        const int row = gidx >> 3, c = gidx & 7;
        const int n = base + row;
        uint4 v = make_uint4(0u, 0u, 0u, 0u);
        if (n < N) {
            const float4 a = reinterpret_cast<const float4*>(d_agg)[n * 16 + c * 2];
            const float4 b = reinterpret_cast<const float4*>(d_agg)[n * 16 + c * 2 + 1];
            v = make_uint4(pack_bf2(a.x, a.y), pack_bf2(a.z, a.w),
                           pack_bf2(b.x, b.y), pack_bf2(b.z, b.w));
        }
        const int boff = row * 128 + ((c * 16) ^ ((row & 7) << 4));
        *reinterpret_cast<uint4*>(smem + NOFF_AG + boff) = v;
    }
    __syncthreads();

    const int rowbase = wid * 16;
    const int l4 = lane & 3;
    const int rgrp = lane >> 2;
    const int r0 = rowbase + rgrp;
    const int r1 = r0 + 8;
    const int n0 = base + r0, n1 = base + r1;

    float acc[8][4];
    uint32_t af[16];

    // GEMM1: t = silu([h|agg] @ Wh1 + bh1)
    acc_init_bias(acc, sbh1, l4);
    gemm_smemA(acc, su + NOFF_AH, su + NOFF_WA, rowbase, lane);
    gemm_smemA(acc, su + NOFF_AG, su + NOFF_WB, rowbase, lane);
#pragma unroll
    for (int nt = 0; nt < 8; ++nt) {
        acc[nt][0] = silu_f(acc[nt][0]);
        acc[nt][1] = silu_f(acc[nt][1]);
        acc[nt][2] = silu_f(acc[nt][2]);
        acc[nt][3] = silu_f(acc[nt][3]);
    }
    make_afrag(acc, af);

    // GEMM2: h_update = t @ Wh2 + bh2 ; out = hsum + h_update
    acc_init_bias(acc, sbh2, l4);
    gemm_regA(acc, af, su + NOFF_W2, lane);
#pragma unroll
    for (int nt = 0; nt < 8; ++nt) {
        const int cb = nt * 8 + 2 * l4;
        if (n0 < N) {
            const float2 hv = *reinterpret_cast<const float2*>(d_hsum + (size_t)n0 * 64 + cb);
            *reinterpret_cast<float2*>(out + (size_t)n0 * 64 + cb) =
                make_float2(acc[nt][0] + hv.x, acc[nt][1] + hv.y);
        }
        if (n1 < N) {
            const float2 hv = *reinterpret_cast<const float2*>(d_hsum + (size_t)n1 * 64 + cb);
            *reinterpret_cast<float2*>(out + (size_t)n1 * 64 + cb) =
                make_float2(acc[nt][2] + hv.x, acc[nt][3] + hv.y);
        }
    }

    // pos update (one thread per row: l4 == 0 handles r0 and r1)
    if (l4 == 0) {
        float* out_pos = out + (size_t)N * 64;
        if (n0 < N) {
            const float dg = fmaxf(d_deg[n0], 1.0f);
            const float2 pa = *reinterpret_cast<const float2*>(d_posacc + n0 * 2);
            const float2 pp = reinterpret_cast<const float2*>(pos)[n0];
            *reinterpret_cast<float2*>(out_pos + n0 * 2) =
                make_float2(pp.x + pa.x / dg, pp.y + pa.y / dg);
        }
        if (n1 < N) {
            const float dg = fmaxf(d_deg[n1], 1.0f);
            const float2 pa = *reinterpret_cast<const float2*>(d_posacc + n1 * 2);
            const float2 pp = reinterpret_cast<const float2*>(pos)[n1];
            *reinterpret_cast<float2*>(out_pos + n1 * 2) =
                make_float2(pp.x + pa.x / dg, pp.y + pa.y / dg);
        }
    }
}

// ---------------------------------------------------------------------------
extern "C" void kernel_launch(void* const* d_in, const int* in_sizes, int n_in,
                              void* d_out, int out_size)
{
    const float* h      = (const float*)d_in[0];
    const float* pos    = (const float*)d_in[1];
    const float* h_init = (const float*)d_in[2];
    const float* Wm1    = (const float*)d_in[3];
    const float* bm1    = (const float*)d_in[4];
    const float* Wm2    = (const float*)d_in[5];
    const float* bm2    = (const float*)d_in[6];
    const float* Wp1    = (const float*)d_in[7];
    const float* bp1    = (const float*)d_in[8];
    const float* Wp2    = (const float*)d_in[9];
    const float* bp2    = (const float*)d_in[10];
    const float* Wh1    = (const float*)d_in[11];
    const float* bh1    = (const float*)d_in[12];
    const float* Wh2    = (const float*)d_in[13];
    const float* bh2    = (const float*)d_in[14];
    const void*  ei     = d_in[15];

    const int N = in_sizes[0] / 64;
    const int E = in_sizes[15] / 2;
    float* out = (float*)d_out;

    cudaFuncSetAttribute(egnn_edge_kernel,
                         cudaFuncAttributeMaxDynamicSharedMemorySize, EDGE_SMEM_BYTES);
    cudaFuncSetAttribute(egnn_node_kernel,
                         cudaFuncAttributeMaxDynamicSharedMemorySize, NODE_SMEM_BYTES);

    egnn_detect_kernel<<<1, 256>>>((const long long*)ei, E);
    egnn_cvt_kernel<<<(2 * E + 255) / 256, 256>>>(ei, E);
    egnn_init_kernel<<<(N * 16 + 255) / 256, 256>>>(h, h_init, N);

    const int nTiles = (E + TILE_E - 1) / TILE_E;
    int eblocks = nTiles < 296 ? nTiles : 296;   // 2 CTAs/SM
    egnn_edge_kernel<<<eblocks, NTHREADS, EDGE_SMEM_BYTES>>>(
        pos, Wm1, bm1, Wm2, bm2, Wp1, bp1, Wp2, bp2, E, N);

    const int nblocks = (N + NT_TILE - 1) / NT_TILE;
    egnn_node_kernel<<<nblocks, NT_THREADS, NODE_SMEM_BYTES>>>(
        pos, Wh1, bh1, Wh2, bh2, out, N);
}

// round 17
// speedup vs baseline: 2.5376x; 1.2844x over previous
#include <cuda_runtime.h>
#include <cuda_bf16.h>
#include <stdint.h>

// ---------------------------------------------------------------------------
// EGNN / SpatialNCA step.  N=50000 nodes, D=64, E=800000 edges, P=2.
//
// R17 = R16 (bf16 mma edge+node pipelines, 2 edge CTAs/SM) +
//  - silu via single-MUFU tanh.approx (halves special-function pressure)
//  - deg accumulation moved into the cvt kernel (off the edge critical path)
// ---------------------------------------------------------------------------

typedef unsigned long long ull;

#define MAXN 50000
#define MAXD 64
#define MAXE 800000

// scratch (device globals: allocation-free rule)
__device__ __align__(16) float d_hsum[MAXN * MAXD];
__device__ __align__(16) __nv_bfloat16 d_hsum_hi[MAXN * MAXD];
__device__ __align__(16) float d_agg[MAXN * MAXD];
__device__ __align__(16) float d_posacc[MAXN * 2];
__device__ float d_deg[MAXN];
__device__ int   d_src[MAXE];
__device__ int   d_dst[MAXE];
__device__ int   d_e32flag;   // 1 if edge_index buffer is int32, 0 if int64

// ---- small helpers ----------------------------------------------------------
__device__ __forceinline__ uint32_t smem_to_u32(const void* p) {
    uint32_t a;
    asm("{ .reg .u64 t; cvta.to.shared.u64 t, %1; cvt.u32.u64 %0, t; }"
        : "=r"(a) : "l"(p));
    return a;
}
// silu(x) = 0.5*x*(1 + tanh(x/2)) — single MUFU via tanh.approx (err ~2^-11,
// below the bf16 rounding noise already in the pipeline)
__device__ __forceinline__ float silu_f(float x) {
    float t;
    asm("tanh.approx.f32 %0, %1;" : "=f"(t) : "f"(0.5f * x));
    return 0.5f * x * (1.0f + t);
}
__device__ __forceinline__ void red_add_v2(float* p, float x, float y) {
    asm volatile("red.global.add.v2.f32 [%0], {%1, %2};"
                 :: "l"(p), "f"(x), "f"(y) : "memory");
}

// ---- mma / ldmatrix primitives (sm_80-compatible, run on sm_100 HMMA) -------
__device__ __forceinline__ void ldsm_x4(uint32_t& r0, uint32_t& r1,
                                        uint32_t& r2, uint32_t& r3, uint32_t addr) {
    asm volatile("ldmatrix.sync.aligned.m8n8.x4.shared.b16 {%0,%1,%2,%3}, [%4];"
                 : "=r"(r0), "=r"(r1), "=r"(r2), "=r"(r3) : "r"(addr));
}
__device__ __forceinline__ void mma_bf16(float* c,
                                         uint32_t a0, uint32_t a1, uint32_t a2, uint32_t a3,
                                         uint32_t b0, uint32_t b1) {
    asm volatile("mma.sync.aligned.m16n8k16.row.col.f32.bf16.bf16.f32 "
                 "{%0,%1,%2,%3}, {%4,%5,%6,%7}, {%8,%9}, {%0,%1,%2,%3};"
                 : "+f"(c[0]), "+f"(c[1]), "+f"(c[2]), "+f"(c[3])
                 : "r"(a0), "r"(a1), "r"(a2), "r"(a3), "r"(b0), "r"(b1));
}

// lane-specific ldmatrix.x4 address into a [rows x 64 bf16] SW128 plane
__device__ __forceinline__ uint32_t lds_addr(uint32_t base, int rowbase, int kc, int lane) {
    const int quad = lane >> 3, r8 = lane & 7;
    const int row = rowbase + r8 + (quad & 1) * 8;
    const int kb = kc * 32 + (quad >> 1) * 16;
    return base + row * 128 + (kb ^ ((row & 7) << 4));
}

// ---- bf16 pack helpers --------------------------------------------------------
__device__ __forceinline__ uint32_t pack_bf2(float x, float y) {
    __nv_bfloat162 h = __floats2bfloat162_rn(x, y);
    return *reinterpret_cast<uint32_t*>(&h);
}

// ---- shared GEMM building blocks ---------------------------------------------
__device__ __forceinline__ void gemm_smemA(
    float acc[8][4], uint32_t aP, uint32_t bP, int rowbase, int lane)
{
#pragma unroll
    for (int kc = 0; kc < 4; ++kc) {
        uint32_t ah[4];
        ldsm_x4(ah[0], ah[1], ah[2], ah[3], lds_addr(aP, rowbase, kc, lane));
#pragma unroll
        for (int p = 0; p < 4; ++p) {
            uint32_t bh[4];
            ldsm_x4(bh[0], bh[1], bh[2], bh[3], lds_addr(bP, 16 * p, kc, lane));
            mma_bf16(acc[2 * p],     ah[0], ah[1], ah[2], ah[3], bh[0], bh[2]);
            mma_bf16(acc[2 * p + 1], ah[0], ah[1], ah[2], ah[3], bh[1], bh[3]);
        }
    }
}
__device__ __forceinline__ void gemm_regA(
    float acc[8][4], const uint32_t af[16], uint32_t bP, int lane)
{
#pragma unroll
    for (int kc = 0; kc < 4; ++kc) {
        const uint32_t* ah = af + 4 * kc;
#pragma unroll
        for (int p = 0; p < 4; ++p) {
            uint32_t bh[4];
            ldsm_x4(bh[0], bh[1], bh[2], bh[3], lds_addr(bP, 16 * p, kc, lane));
            mma_bf16(acc[2 * p],     ah[0], ah[1], ah[2], ah[3], bh[0], bh[2]);
            mma_bf16(acc[2 * p + 1], ah[0], ah[1], ah[2], ah[3], bh[1], bh[3]);
        }
    }
}
__device__ __forceinline__ void make_afrag(const float v[8][4], uint32_t af[16])
{
#pragma unroll
    for (int kk = 0; kk < 4; ++kk) {
        af[4*kk + 0] = pack_bf2(v[2*kk][0],   v[2*kk][1]);
        af[4*kk + 1] = pack_bf2(v[2*kk][2],   v[2*kk][3]);
        af[4*kk + 2] = pack_bf2(v[2*kk+1][0], v[2*kk+1][1]);
        af[4*kk + 3] = pack_bf2(v[2*kk+1][2], v[2*kk+1][3]);
    }
}
__device__ __forceinline__ void acc_init_bias(float acc[8][4], const float* sb, int l4) {
#pragma unroll
    for (int nt = 0; nt < 8; ++nt) {
        const int cb = nt * 8 + 2 * l4;
        const float b0 = sb[cb], b1 = sb[cb + 1];
        acc[nt][0] = b0; acc[nt][1] = b1;
        acc[nt][2] = b0; acc[nt][3] = b1;
    }
}

// ---- edge kernel config (2 CTAs/SM) -------------------------------------------
constexpr int TILE_E   = 192;               // edges per tile (12 warps x 16)
constexpr int NTHREADS = 384;

constexpr int OFF_SIDX = 0;                 // 192 ints
constexpr int OFF_D2   = 768;               // 192 f32
constexpr int OFF_REL  = 1536;              // 384 f32 -> 3072
constexpr int OFF_B1   = 3072;
constexpr int OFF_B2   = 3328;
constexpr int OFF_BP1  = 3584;
constexpr int OFF_W1C  = 3840;
constexpr int OFF_WP2  = 4096;
constexpr int OFF_BP2  = 4352;
// weight B-tiles [n=64][k=64] bf16 SW128 (8KB each)
constexpr int OFF_B1A  = 4608;
constexpr int OFF_B1B  = 12800;
constexpr int OFF_B2W  = 20992;
constexpr int OFF_BP1W = 29184;
// A-tiles [192 x 64] bf16 SW128 (24576 B each)
constexpr int OFF_ADST = 37376;
constexpr int OFF_ASRC = 61952;
constexpr int EDGE_SMEM_BYTES = 86528;      // 84.5 KB -> 2 CTAs/SM

// ---- node kernel config (mma) --------------------------------------------------
constexpr int NT_TILE    = 128;             // nodes per tile (8 warps x 16)
constexpr int NT_THREADS = 256;

constexpr int NOFF_WA  = 0;                 // Wh1 k=0..63  B-tile, 8KB
constexpr int NOFF_WB  = 8192;              // Wh1 k=64..127, 8KB
constexpr int NOFF_W2  = 16384;             // Wh2, 8KB
constexpr int NOFF_BH1 = 24576;             // 256B
constexpr int NOFF_BH2 = 24832;             // 256B
constexpr int NOFF_AH  = 25088;             // 128 x 128B = 16384
constexpr int NOFF_AG  = 41472;             // 16384 -> end 57856
constexpr int NODE_SMEM_BYTES = 57856;      // 56.5 KB -> 3 CTAs/SM

// ---------------------------------------------------------------------------
// Kernel 0a: edge_index dtype detect.
// ---------------------------------------------------------------------------
__global__ void egnn_detect_kernel(const long long* __restrict__ ei, const int E)
{
    __shared__ int bad;
    if (threadIdx.x == 0) bad = 0;
    __syncthreads();
    const int cnt = E < 1024 ? E : 1024;
    for (int i = threadIdx.x; i < cnt; i += blockDim.x) {
        const long long v = ei[i];
        if (v < 0 || v > 0x7FFFFFFFLL) bad = 1;
    }
    __syncthreads();
    if (threadIdx.x == 0) d_e32flag = bad;
}

// Kernel 0b: normalize indices + accumulate deg (runs AFTER init zeroes deg).
__global__ void egnn_cvt_kernel(const void* __restrict__ ei, const int E, const int N)
{
    const int i = blockIdx.x * blockDim.x + threadIdx.x;
    if (i >= 2 * E) return;
    int v;
    if (d_e32flag) v = ((const int*)ei)[i];
    else           v = (int)(((const long long*)ei)[i]);
    if (i < E) {
        d_src[i] = v;
    } else {
        d_dst[i - E] = v;
        if ((unsigned)v < (unsigned)N) atomicAdd(&d_deg[v], 1.0f);
    }
}

// ---------------------------------------------------------------------------
// Kernel 1: hsum = h + h_init; bf16 plane; zero accumulators.
// ---------------------------------------------------------------------------
__global__ void egnn_init_kernel(const float* __restrict__ h,
                                 const float* __restrict__ hi, const int N)
{
    const int i = blockIdx.x * blockDim.x + threadIdx.x;
    const int n4 = N * 16;
    if (i < n4) {
        const float4 a = reinterpret_cast<const float4*>(h)[i];
        const float4 b = reinterpret_cast<const float4*>(hi)[i];
        float4 s;
        s.x = a.x + b.x; s.y = a.y + b.y; s.z = a.z + b.z; s.w = a.w + b.w;
        reinterpret_cast<float4*>(d_hsum)[i] = s;
        reinterpret_cast<uint2*>(d_hsum_hi)[i] =
            make_uint2(pack_bf2(s.x, s.y), pack_bf2(s.z, s.w));
        reinterpret_cast<float4*>(d_agg)[i] = make_float4(0.f, 0.f, 0.f, 0.f);
    }
    if (i < N) d_deg[i] = 0.0f;
    if (i < N * 2) d_posacc[i] = 0.0f;
}

// ---------------------------------------------------------------------------
// Kernel 2: persistent mma.sync edge kernel. 384 threads; 192-edge tiles;
// 2 CTAs per SM for cross-CTA phase overlap.
// ---------------------------------------------------------------------------
__global__ void __launch_bounds__(NTHREADS, 2)
egnn_edge_kernel(const float* __restrict__ pos,
                 const float* __restrict__ Wm1, const float* __restrict__ bm1,
                 const float* __restrict__ Wm2, const float* __restrict__ bm2,
                 const float* __restrict__ Wp1, const float* __restrict__ bp1,
                 const float* __restrict__ Wp2, const float* __restrict__ bp2,
                 const int E, const int N)
{
    extern __shared__ char smem[];
    const uint32_t su = smem_to_u32(smem);
    const int tid = threadIdx.x;
    const int wid = tid >> 5;
    const int lane = tid & 31;

    // ---- stage weights as bf16 B-tiles (B[n][k] = W[k][n], SW128) ----
    for (int idx = tid; idx < 4096; idx += NTHREADS) {
        const int n = idx >> 6, k = idx & 63;
        const int off = n * 128 + ((k * 2) ^ ((n & 7) << 4));
        *reinterpret_cast<__nv_bfloat16*>(smem + OFF_B1A + off) =
            __float2bfloat16_rn(Wm1[k * 64 + n]);
        *reinterpret_cast<__nv_bfloat16*>(smem + OFF_B1B + off) =
            __float2bfloat16_rn(Wm1[(64 + k) * 64 + n]);
        *reinterpret_cast<__nv_bfloat16*>(smem + OFF_B2W + off) =
            __float2bfloat16_rn(Wm2[k * 64 + n]);
        *reinterpret_cast<__nv_bfloat16*>(smem + OFF_BP1W + off) =
            __float2bfloat16_rn(Wp1[k * 64 + n]);
    }
    if (tid < 64) {
        ((float*)(smem + OFF_B1 ))[tid] = bm1[tid];
        ((float*)(smem + OFF_B2 ))[tid] = bm2[tid];
        ((float*)(smem + OFF_BP1))[tid] = bp1[tid];
        ((float*)(smem + OFF_W1C))[tid] = Wm1[128 * 64 + tid];
        ((float*)(smem + OFF_WP2))[tid] = Wp2[tid];
    }
    if (tid == 0) ((float*)(smem + OFF_BP2))[0] = bp2[0];
    __syncthreads();

    int* sidx   = (int*)(smem + OFF_SIDX);
    float* sd2  = (float*)(smem + OFF_D2);
    float* srel = (float*)(smem + OFF_REL);
    const float* sb1  = (const float*)(smem + OFF_B1);
    const float* sb2  = (const float*)(smem + OFF_B2);
    const float* sbp1 = (const float*)(smem + OFF_BP1);
    const float* sw1c = (const float*)(smem + OFF_W1C);
    const float* swp2 = (const float*)(smem + OFF_WP2);

    const int rowbase = wid * 16;
    const int l4 = lane & 3;
    const int rgrp = lane >> 2;
    const int r0 = rowbase + rgrp;
    const int r1 = r0 + 8;

    const int nTiles = (E + TILE_E - 1) / TILE_E;

    for (int t = blockIdx.x; t < nTiles; t += gridDim.x) {
        const int eBase = t * TILE_E;

        // ---- gather phase (coalesced: 8 lanes per 128B bf16 row) ----
        if (tid < TILE_E) {
            const int e = eBase + tid;
            int dn = -1, sn = -1;
            if (e < E) { dn = d_dst[e]; sn = d_src[e]; }
            if ((unsigned)dn >= (unsigned)N) dn = -1;
            if ((unsigned)sn >= (unsigned)N) sn = -1;
            sidx[tid] = dn;
            float rx = 0.f, ry = 0.f;
            if (dn >= 0 && sn >= 0) {
                const float2 pd = reinterpret_cast<const float2*>(pos)[dn];
                const float2 ps = reinterpret_cast<const float2*>(pos)[sn];
                rx = pd.x - ps.x; ry = pd.y - ps.y;
            }
            srel[2 * tid] = rx; srel[2 * tid + 1] = ry;
            sd2[tid] = rx * rx + ry * ry;
        }
#pragma unroll
        for (int i = 0; i < 8; ++i) {
            const int gidx = tid + i * NTHREADS;      // 0..3071
            const int row  = gidx >> 3;               // 0..383
            const int c    = gidx & 7;
            const bool dstp = (row < TILE_E);
            const int er = dstp ? row : row - TILE_E;
            const int e = eBase + er;
            int node = -1;
            if (e < E) node = dstp ? d_dst[e] : d_src[e];
            if ((unsigned)node >= (unsigned)N) node = -1;
            uint4 vh = make_uint4(0u, 0u, 0u, 0u);
            if (node >= 0)
                vh = reinterpret_cast<const uint4*>(d_hsum_hi)[node * 8 + c];
            const int boff = er * 128 + ((c * 16) ^ ((er & 7) << 4));
            char* aT = smem + (dstp ? OFF_ADST : OFF_ASRC);
            *reinterpret_cast<uint4*>(aT + boff) = vh;
        }
        __syncthreads();

        float acc[8][4];
        uint32_t af[16];

        // ===== GEMM1 =====
        acc_init_bias(acc, sb1, l4);
        gemm_smemA(acc, su + OFF_ADST, su + OFF_B1A, rowbase, lane);
        gemm_smemA(acc, su + OFF_ASRC, su + OFF_B1B, rowbase, lane);
        {
            const float dd0 = sd2[r0], dd1 = sd2[r1];
#pragma unroll
            for (int nt = 0; nt < 8; ++nt) {
                const int cb = nt * 8 + 2 * l4;
                const float w0 = sw1c[cb], w1 = sw1c[cb + 1];
                acc[nt][0] = silu_f(acc[nt][0] + dd0 * w0);
                acc[nt][1] = silu_f(acc[nt][1] + dd0 * w1);
                acc[nt][2] = silu_f(acc[nt][2] + dd1 * w0);
                acc[nt][3] = silu_f(acc[nt][3] + dd1 * w1);
            }
            make_afrag(acc, af);
        }

        // ===== GEMM2 =====
        acc_init_bias(acc, sb2, l4);
        gemm_regA(acc, af, su + OFF_B2W, lane);
        {
            const int dn0 = sidx[r0], dn1 = sidx[r1];
            float* agg0 = d_agg + (size_t)(dn0 < 0 ? 0 : dn0) * 64;
            float* agg1 = d_agg + (size_t)(dn1 < 0 ? 0 : dn1) * 64;
#pragma unroll
            for (int nt = 0; nt < 8; ++nt) {
                const int cb = nt * 8 + 2 * l4;
                acc[nt][0] = silu_f(acc[nt][0]);
                acc[nt][1] = silu_f(acc[nt][1]);
                acc[nt][2] = silu_f(acc[nt][2]);
                acc[nt][3] = silu_f(acc[nt][3]);
                if (dn0 >= 0) red_add_v2(agg0 + cb, acc[nt][0], acc[nt][1]);
                if (dn1 >= 0) red_add_v2(agg1 + cb, acc[nt][2], acc[nt][3]);
            }
            make_afrag(acc, af);
        }

        // ===== GEMM3 =====
        acc_init_bias(acc, sbp1, l4);
        gemm_regA(acc, af, su + OFF_BP1W, lane);
        {
            float p0 = 0.f, p1 = 0.f;
#pragma unroll
            for (int nt = 0; nt < 8; ++nt) {
                const int cb = nt * 8 + 2 * l4;
                const float w0 = swp2[cb], w1 = swp2[cb + 1];
                p0 += silu_f(acc[nt][0]) * w0 + silu_f(acc[nt][1]) * w1;
                p1 += silu_f(acc[nt][2]) * w0 + silu_f(acc[nt][3]) * w1;
            }
            p0 += __shfl_xor_sync(0xFFFFFFFFu, p0, 1);
            p0 += __shfl_xor_sync(0xFFFFFFFFu, p0, 2);
            p1 += __shfl_xor_sync(0xFFFFFFFFu, p1, 1);
            p1 += __shfl_xor_sync(0xFFFFFFFFu, p1, 2);
            if (l4 == 0) {
                const float bp2v = ((const float*)(smem + OFF_BP2))[0];
                const int dn0 = sidx[r0], dn1 = sidx[r1];
                if (dn0 >= 0) {
                    const float w = p0 + bp2v;
                    red_add_v2(&d_posacc[dn0 * 2], srel[2 * r0] * w, srel[2 * r0 + 1] * w);
                }
                if (dn1 >= 0) {
                    const float w = p1 + bp2v;
                    red_add_v2(&d_posacc[dn1 * 2], srel[2 * r1] * w, srel[2 * r1 + 1] * w);
                }
            }
        }
        __syncthreads();
    }
}

// ---------------------------------------------------------------------------
// Kernel 3: node update (phi_h) via bf16 mma. 256 threads; 128-node tiles.
// ---------------------------------------------------------------------------
__global__ void __launch_bounds__(NT_THREADS, 3)
egnn_node_kernel(const float* __restrict__ pos,
                 const float* __restrict__ Wh1, const float* __restrict__ bh1,
                 const float* __restrict__ Wh2, const float* __restrict__ bh2,
                 float* __restrict__ out, const int N)
{
    extern __shared__ char smem[];
    const uint32_t su = smem_to_u32(smem);
    const int tid = threadIdx.x;
    const int wid = tid >> 5;
    const int lane = tid & 31;

    for (int idx = tid; idx < 4096; idx += NT_THREADS) {
        const int n = idx >> 6, k = idx & 63;
        const int off = n * 128 + ((k * 2) ^ ((n & 7) << 4));
        *reinterpret_cast<__nv_bfloat16*>(smem + NOFF_WA + off) =
            __float2bfloat16_rn(Wh1[k * 64 + n]);
        *reinterpret_cast<__nv_bfloat16*>(smem + NOFF_WB + off) =
            __float2bfloat16_rn(Wh1[(64 + k) * 64 + n]);
        *reinterpret_cast<__nv_bfloat16*>(smem + NOFF_W2 + off) =
            __float2bfloat16_rn(Wh2[k * 64 + n]);
    }
    if (tid < 64) {
        ((float*)(smem + NOFF_BH1))[tid] = bh1[tid];
        ((float*)(smem + NOFF_BH2))[tid] = bh2[tid];
    }
    __syncthreads();

    const float* sbh1 = (const float*)(smem + NOFF_BH1);
    const float* sbh2 = (const float*)(smem + NOFF_BH2);

    const int base = blockIdx.x * NT_TILE;

#pragma unroll
    for (int i = 0; i < 4; ++i) {
        const int gidx = tid + i * NT_THREADS;
        const int row = gidx >> 3, c = gidx & 7;
        const int n = base + row;
        uint4 v = make_uint4(0u, 0u, 0u, 0u);
        if (n < N) v = reinterpret_cast<const uint4*>(d_hsum_hi)[n * 8 + c];
        const int boff = row * 128 + ((c * 16) ^ ((row & 7) << 4));
        *reinterpret_cast<uint4*>(smem + NOFF_AH + boff) = v;
    }
#pragma unroll
    for (int i = 0; i < 4; ++i) {
        const int gidx = tid + i * NT_THREADS;
        const int row = gidx >> 3, c = gidx & 7;
        const int n = base + row;
        uint4 v = make_uint4(0u, 0u, 0u, 0u);
        if (n < N) {
            const float4 a = reinterpret_cast<const float4*>(d_agg)[n * 16 + c * 2];
            const float4 b = reinterpret_cast<const float4*>(d_agg)[n * 16 + c * 2 + 1];
            v = make_uint4(pack_bf2(a.x, a.y), pack_bf2(a.z, a.w),
                           pack_bf2(b.x, b.y), pack_bf2(b.z, b.w));
        }
        const int boff = row * 128 + ((c * 16) ^ ((row & 7) << 4));
        *reinterpret_cast<uint4*>(smem + NOFF_AG + boff) = v;
    }
    __syncthreads();

    const int rowbase = wid * 16;
    const int l4 = lane & 3;
    const int rgrp = lane >> 2;
    const int r0 = rowbase + rgrp;
    const int r1 = r0 + 8;
    const int n0 = base + r0, n1 = base + r1;

    float acc[8][4];
    uint32_t af[16];

    acc_init_bias(acc, sbh1, l4);
    gemm_smemA(acc, su + NOFF_AH, su + NOFF_WA, rowbase, lane);
    gemm_smemA(acc, su + NOFF_AG, su + NOFF_WB, rowbase, lane);
#pragma unroll
    for (int nt = 0; nt < 8; ++nt) {
        acc[nt][0] = silu_f(acc[nt][0]);
        acc[nt][1] = silu_f(acc[nt][1]);
        acc[nt][2] = silu_f(acc[nt][2]);
        acc[nt][3] = silu_f(acc[nt][3]);
    }
    make_afrag(acc, af);

    acc_init_bias(acc, sbh2, l4);
    gemm_regA(acc, af, su + NOFF_W2, lane);
#pragma unroll
    for (int nt = 0; nt < 8; ++nt) {
        const int cb = nt * 8 + 2 * l4;
        if (n0 < N) {
            const float2 hv = *reinterpret_cast<const float2*>(d_hsum + (size_t)n0 * 64 + cb);
            *reinterpret_cast<float2*>(out + (size_t)n0 * 64 + cb) =
                make_float2(acc[nt][0] + hv.x, acc[nt][1] + hv.y);
        }
        if (n1 < N) {
            const float2 hv = *reinterpret_cast<const float2*>(d_hsum + (size_t)n1 * 64 + cb);
            *reinterpret_cast<float2*>(out + (size_t)n1 * 64 + cb) =
                make_float2(acc[nt][2] + hv.x, acc[nt][3] + hv.y);
        }
    }

    if (l4 == 0) {
        float* out_pos = out + (size_t)N * 64;
        if (n0 < N) {
            const float dg = fmaxf(d_deg[n0], 1.0f);
            const float2 pa = *reinterpret_cast<const float2*>(d_posacc + n0 * 2);
            const float2 pp = reinterpret_cast<const float2*>(pos)[n0];
            *reinterpret_cast<float2*>(out_pos + n0 * 2) =
                make_float2(pp.x + pa.x / dg, pp.y + pa.y / dg);
        }
        if (n1 < N) {
            const float dg = fmaxf(d_deg[n1], 1.0f);
            const float2 pa = *reinterpret_cast<const float2*>(d_posacc + n1 * 2);
            const float2 pp = reinterpret_cast<const float2*>(pos)[n1];
            *reinterpret_cast<float2*>(out_pos + n1 * 2) =
                make_float2(pp.x + pa.x / dg, pp.y + pa.y / dg);
        }
    }
}

// ---------------------------------------------------------------------------
extern "C" void kernel_launch(void* const* d_in, const int* in_sizes, int n_in,
                              void* d_out, int out_size)
{
    const float* h      = (const float*)d_in[0];
    const float* pos    = (const float*)d_in[1];
    const float* h_init = (const float*)d_in[2];
    const float* Wm1    = (const float*)d_in[3];
    const float* bm1    = (const float*)d_in[4];
    const float* Wm2    = (const float*)d_in[5];
    const float* bm2    = (const float*)d_in[6];
    const float* Wp1    = (const float*)d_in[7];
    const float* bp1    = (const float*)d_in[8];
    const float* Wp2    = (const float*)d_in[9];
    const float* bp2    = (const float*)d_in[10];
    const float* Wh1    = (const float*)d_in[11];
    const float* bh1    = (const float*)d_in[12];
    const float* Wh2    = (const float*)d_in[13];
    const float* bh2    = (const float*)d_in[14];
    const void*  ei     = d_in[15];

    const int N = in_sizes[0] / 64;
    const int E = in_sizes[15] / 2;
    float* out = (float*)d_out;

    cudaFuncSetAttribute(egnn_edge_kernel,
                         cudaFuncAttributeMaxDynamicSharedMemorySize, EDGE_SMEM_BYTES);
    cudaFuncSetAttribute(egnn_node_kernel,
                         cudaFuncAttributeMaxDynamicSharedMemorySize, NODE_SMEM_BYTES);

    // init first (zeroes deg), then detect, then cvt (accumulates deg)
    egnn_init_kernel<<<(N * 16 + 255) / 256, 256>>>(h, h_init, N);
    egnn_detect_kernel<<<1, 256>>>((const long long*)ei, E);
    egnn_cvt_kernel<<<(2 * E + 255) / 256, 256>>>(ei, E, N);

    const int nTiles = (E + TILE_E - 1) / TILE_E;
    int eblocks = nTiles < 296 ? nTiles : 296;   // 2 CTAs/SM
    egnn_edge_kernel<<<eblocks, NTHREADS, EDGE_SMEM_BYTES>>>(
        pos, Wm1, bm1, Wm2, bm2, Wp1, bp1, Wp2, bp2, E, N);

    const int nblocks = (N + NT_TILE - 1) / NT_TILE;
    egnn_node_kernel<<<nblocks, NT_THREADS, NODE_SMEM_BYTES>>>(
        pos, Wh1, bh1, Wh2, bh2, out, N);
}